// round 4
// baseline (speedup 1.0000x reference)
#include <cuda_runtime.h>
#include <cuda_bf16.h>
#include <math.h>

// ---------------------------------------------------------------------------
// RTE forward (word-by-word attention entailment model), fp32.
// B=128, T=128, NDIM=512, EMB=300, G=3*NDIM=1536, VOCAB=50000.
//
// Strategy:
//   * Hoist all loop-invariant GEMMs out of the recurrences:
//       Gi_p/Gi_h  = E[tok] @ Wih^T + bih           (gather fused into GEMM)
//       Yw         = o_p @ W_y
//       hWh        = o_h @ W_h
//       gihp       = o_h @ mWih[:,512:]^T + m_bih
//   * Each sequential GRU step = ONE fused kernel: gate-packed Whh GEMM
//     (rows n*3+g) + gate nonlinearity + masked update.
//   * Attention step = 4 kernels: s-GEMM(+addend), alpha (tanh dot), softmax+
//     context, fused match-GRU step (two K=512 dots per gate).
// ---------------------------------------------------------------------------

#define B_   128
#define T_   128
#define N_   512
#define E_   300
#define G_   1536
#define TBN_ (T_ * B_)   // 16384

// ------------------------------- scratch (static device memory) ------------
__device__ float g_GiP[TBN_ * G_];     // premise input gates, [t*B+b][1536]
__device__ float g_GiH[TBN_ * G_];     // hypothesis input gates
__device__ float g_oP [TBN_ * N_];     // premise GRU outputs  [t][b][n]
__device__ float g_oH [TBN_ * N_];     // hypothesis GRU outputs
__device__ float g_Yw [TBN_ * N_];     // o_p @ W_y
__device__ float g_hWh[TBN_ * N_];     // o_h @ W_h
__device__ float g_gihp[TBN_ * G_];    // o_h @ mWih_h^T + m_bih
__device__ float g_h0[B_ * N_];        // hidden ping-pong
__device__ float g_h1[B_ * N_];
__device__ float g_r0[B_ * N_];        // match-GRU state ping-pong
__device__ float g_r1[B_ * N_];
__device__ float g_s  [B_ * N_];       // attention s per step
__device__ float g_alpha[B_ * T_];     // attention logits per step
__device__ float g_a  [B_ * N_];       // context vector per step
__device__ float g_maskP[T_ * B_];
__device__ float g_maskH[T_ * B_];
__device__ float g_WyT[N_ * N_];
__device__ float g_WhT[N_ * N_];
__device__ float g_WrT[N_ * N_];
__device__ float g_WpP[G_ * N_];       // gate-packed p_Whh  (row n*3+g)
__device__ float g_bpP[G_];
__device__ float g_WpH[G_ * N_];       // gate-packed h_Whh
__device__ float g_bpH[G_];
__device__ float g_WpM[G_ * N_];       // gate-packed m_Whh
__device__ float g_bpM[G_];
__device__ float g_AihP[G_ * N_];      // gate-packed m_Wih[:, 0:512]
__device__ float g_mWihH[G_ * N_];     // m_Wih[:, 512:1024] (natural gate order)

// ------------------------------- math helpers ------------------------------
__device__ __forceinline__ float sigm_f(float x) {
    return 1.0f / (1.0f + __expf(-x));
}
__device__ __forceinline__ float tanh_f(float x) {
    float e = __expf(-2.0f * fabsf(x));
    float t = (1.0f - e) / (1.0f + e);
    return copysignf(t, x);
}

// ------------------------------- prep kernels ------------------------------
__global__ void make_masks_k(const int* __restrict__ prem,
                             const int* __restrict__ hyp) {
    int i = blockIdx.x * blockDim.x + threadIdx.x;   // i = t*B + b
    if (i < T_ * B_) {
        int t = i >> 7, b = i & 127;
        g_maskP[i] = (prem[b * T_ + t] != 0) ? 1.0f : 0.0f;
        g_maskH[i] = (hyp [b * T_ + t] != 0) ? 1.0f : 0.0f;
    }
}

__global__ void zero_state_k() {
    int i = blockIdx.x * blockDim.x + threadIdx.x;
    if (i < B_ * N_) { g_h0[i] = 0.0f; g_r0[i] = 0.0f; }
}

__global__ void transpose512_k(const float* __restrict__ src,
                               float* __restrict__ dst) {
    int i = blockIdx.x * blockDim.x + threadIdx.x;
    if (i < N_ * N_) {
        int r = i >> 9, c = i & 511;
        dst[c * N_ + r] = src[i];
    }
}

// Wp[(n*3+g)*512 + k] = W[(g*512+n)*ld + coloff + k]
__global__ void pack_gate_k(const float* __restrict__ W,
                            const float* __restrict__ b,
                            float* __restrict__ Wp, float* __restrict__ bp,
                            int ld, int coloff) {
    int i = blockIdx.x * blockDim.x + threadIdx.x;
    if (i < G_ * N_) {
        int j = i >> 9;
        int k = i & 511;
        int n = j / 3, g = j - n * 3;
        Wp[i] = W[(size_t)(g * N_ + n) * ld + coloff + k];
        if (k == 0 && bp) bp[j] = b[g * N_ + n];
    }
}

__global__ void split_mwih_h_k(const float* __restrict__ mWih,
                               float* __restrict__ out) {
    int i = blockIdx.x * blockDim.x + threadIdx.x;
    if (i < G_ * N_) {
        int j = i >> 9, k = i & 511;
        out[i] = mWih[(size_t)j * 1024 + 512 + k];
    }
}

// ------------------------------- big GEMM ----------------------------------
// C[M,N] = Aeff @ Bt^T (+bias[n]) ; Aeff row m = gidx ? A[tok(m)] : A[m]
// tok(m) = gidx[(m%128)*128 + m/128]  (embedding gather fused)
// Tiles: 128x128, TK=16, 256 threads, 8x8 micro-tile.
__global__ void gemm_big_k(const float* __restrict__ A,
                           const int*   __restrict__ gidx,
                           const float* __restrict__ Bt,
                           const float* __restrict__ bias,
                           float* __restrict__ C,
                           int M, int N, int K) {
    __shared__ float As[16][132];
    __shared__ float Bs[16][132];
    int tid = threadIdx.x;
    int tx = tid & 15, ty = tid >> 4;
    int m0 = blockIdx.y * 128, n0 = blockIdx.x * 128;

    float acc[8][8];
#pragma unroll
    for (int i = 0; i < 8; i++)
#pragma unroll
        for (int j = 0; j < 8; j++) acc[i][j] = 0.0f;

    int arow = m0 + (tid >> 1);
    const float* abase;
    if (gidx) {
        int tok = gidx[(arow & 127) * 128 + (arow >> 7)];
        abase = A + (size_t)tok * K;
    } else {
        abase = A + (size_t)arow * K;
    }
    int brow = n0 + (tid >> 1);
    const float* bbase = Bt + (size_t)brow * K;
    int kk = (tid & 1) * 8;

    for (int k0 = 0; k0 < K; k0 += 16) {
#pragma unroll
        for (int i = 0; i < 8; i++) {
            int k = k0 + kk + i;
            As[kk + i][tid >> 1] = (k < K) ? abase[k] : 0.0f;
            Bs[kk + i][tid >> 1] = (k < K) ? bbase[k] : 0.0f;
        }
        __syncthreads();
#pragma unroll
        for (int k = 0; k < 16; k++) {
            float a[8], b[8];
#pragma unroll
            for (int i = 0; i < 8; i++) a[i] = As[k][ty * 8 + i];
#pragma unroll
            for (int j = 0; j < 8; j++) b[j] = Bs[k][tx * 8 + j];
#pragma unroll
            for (int i = 0; i < 8; i++)
#pragma unroll
                for (int j = 0; j < 8; j++) acc[i][j] += a[i] * b[j];
        }
        __syncthreads();
    }
#pragma unroll
    for (int i = 0; i < 8; i++) {
        int row = m0 + ty * 8 + i;
        if (row >= M) continue;
#pragma unroll
        for (int j = 0; j < 8; j++) {
            int col = n0 + tx * 8 + j;
            if (col >= N) continue;
            float v = acc[i][j];
            if (bias) v += bias[col];
            C[(size_t)row * N + col] = v;
        }
    }
}

// ------------------------------- small GEMM --------------------------------
// C[M,N] = A @ Bt^T (+bias[n]) (+addend[m][n]) ; tiles 32x64, 128 threads.
__global__ void gemm_small_k(const float* __restrict__ A,
                             const float* __restrict__ Bt,
                             const float* __restrict__ bias,
                             const float* __restrict__ addend,
                             float* __restrict__ C,
                             int M, int N, int K) {
    __shared__ float As[16][36];
    __shared__ float Bs[16][68];
    int tid = threadIdx.x;
    int tx = tid & 15, ty = tid >> 4;
    int m0 = blockIdx.y * 32, n0 = blockIdx.x * 64;

    float acc[4][4];
#pragma unroll
    for (int i = 0; i < 4; i++)
#pragma unroll
        for (int j = 0; j < 4; j++) acc[i][j] = 0.0f;

    for (int k0 = 0; k0 < K; k0 += 16) {
        {
            int r = tid >> 2, kq = (tid & 3) * 4;
            const float* ap = A + (size_t)(m0 + r) * K + k0 + kq;
#pragma unroll
            for (int i = 0; i < 4; i++) {
                int k = k0 + kq + i;
                As[kq + i][r] = (k < K) ? ap[i] : 0.0f;
            }
        }
        {
            int r = tid >> 1, kq = (tid & 1) * 8;
            const float* bp = Bt + (size_t)(n0 + r) * K + k0 + kq;
#pragma unroll
            for (int i = 0; i < 8; i++) {
                int k = k0 + kq + i;
                Bs[kq + i][r] = (k < K) ? bp[i] : 0.0f;
            }
        }
        __syncthreads();
#pragma unroll
        for (int k = 0; k < 16; k++) {
            float a[4], b[4];
#pragma unroll
            for (int i = 0; i < 4; i++) a[i] = As[k][ty * 4 + i];
#pragma unroll
            for (int j = 0; j < 4; j++) b[j] = Bs[k][tx * 4 + j];
#pragma unroll
            for (int i = 0; i < 4; i++)
#pragma unroll
                for (int j = 0; j < 4; j++) acc[i][j] += a[i] * b[j];
        }
        __syncthreads();
    }
#pragma unroll
    for (int i = 0; i < 4; i++) {
        int row = m0 + ty * 4 + i;
        if (row >= M) continue;
#pragma unroll
        for (int j = 0; j < 4; j++) {
            int col = n0 + tx * 4 + j;
            if (col >= N) continue;
            float v = acc[i][j];
            if (bias)   v += bias[col];
            if (addend) v += addend[(size_t)row * N + col];
            C[(size_t)row * N + col] = v;
        }
    }
}

// ------------------------------- fused GRU step ----------------------------
// gh = h_prev @ Wpack^T + bpack (gate-packed rows n*3+g), then gate math +
// masked h/o update. Grid: (N/16, B/32) = (32,4), 128 threads.
__global__ void gru_step_k(const float* __restrict__ Gi_t,     // [B][1536]
                           const float* __restrict__ h_prev,   // [B][512]
                           const float* __restrict__ o_prev,   // [B][512] | null
                           const float* __restrict__ Wpack,    // [1536][512]
                           const float* __restrict__ bpack,    // [1536]
                           const float* __restrict__ mask_t,   // [B]
                           float* __restrict__ h_out,
                           float* __restrict__ o_out,
                           int first) {
    __shared__ float Hs[16][36];
    __shared__ float Ws[16][50];
    int tid = threadIdx.x;
    int n0 = blockIdx.x * 16, b0 = blockIdx.y * 32;
    int j0 = n0 * 3;
    int tx = tid & 15, ty = tid >> 4;

    float acc[4][3];
#pragma unroll
    for (int i = 0; i < 4; i++)
#pragma unroll
        for (int g = 0; g < 3; g++) acc[i][g] = 0.0f;

    for (int k0 = 0; k0 < N_; k0 += 16) {
        {
            int bl = tid >> 2, kq = (tid & 3) * 4;
            const float* hp = h_prev + (size_t)(b0 + bl) * N_ + k0 + kq;
#pragma unroll
            for (int i = 0; i < 4; i++) Hs[kq + i][bl] = hp[i];
        }
#pragma unroll
        for (int rr = 0; rr < 6; rr++) {
            int e = tid + rr * 128;
            int jl = e >> 4, kq = e & 15;
            Ws[kq][jl] = Wpack[(size_t)(j0 + jl) * N_ + k0 + kq];
        }
        __syncthreads();
#pragma unroll
        for (int k = 0; k < 16; k++) {
            float h[4], w[3];
#pragma unroll
            for (int i = 0; i < 4; i++) h[i] = Hs[k][ty * 4 + i];
#pragma unroll
            for (int g = 0; g < 3; g++) w[g] = Ws[k][tx * 3 + g];
#pragma unroll
            for (int i = 0; i < 4; i++)
#pragma unroll
                for (int g = 0; g < 3; g++) acc[i][g] += h[i] * w[g];
        }
        __syncthreads();
    }
    int n = n0 + tx;
    float br = bpack[j0 + tx * 3 + 0];
    float bz = bpack[j0 + tx * 3 + 1];
    float bn = bpack[j0 + tx * 3 + 2];
#pragma unroll
    for (int i = 0; i < 4; i++) {
        int b = b0 + ty * 4 + i;
        float gir = Gi_t[(size_t)b * G_ + n];
        float giz = Gi_t[(size_t)b * G_ + 512 + n];
        float gin = Gi_t[(size_t)b * G_ + 1024 + n];
        float rg = sigm_f(gir + acc[i][0] + br);
        float zg = sigm_f(giz + acc[i][1] + bz);
        float nn = tanh_f(gin + rg * (acc[i][2] + bn));
        float hp = h_prev[(size_t)b * N_ + n];
        float hr = (1.0f - zg) * nn + zg * hp;
        float m = mask_t[b];
        h_out[(size_t)b * N_ + n] = hr * m + hp * (1.0f - m);
        o_out[(size_t)b * N_ + n] =
            first ? hr : (hr * m + o_prev[(size_t)b * N_ + n] * (1.0f - m));
    }
}

// ------------------------------- attention: alpha --------------------------
// alpha[b][t'] = sum_n tanh(Yw[t'][b][n] + s[b][n]) * Walpha[n] - 1000*(1-mP)
// One warp per (b,t'); 2048 blocks x 256 threads.
__global__ void attn_alpha_k(const float* __restrict__ Walpha) {
    int gw = (blockIdx.x * blockDim.x + threadIdx.x) >> 5;
    int lane = threadIdx.x & 31;
    if (gw >= B_ * T_) return;
    int b = gw >> 7, tp = gw & 127;
    const float* yw = g_Yw + ((size_t)tp * B_ + b) * N_;
    const float* sb = g_s + (size_t)b * N_;
    float acc = 0.0f;
#pragma unroll 4
    for (int n = lane; n < N_; n += 32)
        acc += tanh_f(yw[n] + sb[n]) * Walpha[n];
#pragma unroll
    for (int o = 16; o; o >>= 1) acc += __shfl_xor_sync(0xffffffffu, acc, o);
    if (lane == 0)
        g_alpha[b * T_ + tp] = acc - 1000.0f * (1.0f - g_maskP[tp * B_ + b]);
}

// ------------------------------- attention: softmax + context --------------
// One block per b. softmax over t', then a[b][n] = sum_t' w[t'] * Y[t'][b][n].
__global__ void attn_ctx_k() {
    __shared__ float w[T_];
    int b = blockIdx.x, tid = threadIdx.x;
    if (tid < T_) w[tid] = g_alpha[b * T_ + tid];
    __syncthreads();
    if (tid < 32) {
        float mx = -1e30f;
        for (int t = tid; t < T_; t += 32) mx = fmaxf(mx, w[t]);
#pragma unroll
        for (int o = 16; o; o >>= 1)
            mx = fmaxf(mx, __shfl_xor_sync(0xffffffffu, mx, o));
        float sm = 0.0f;
        for (int t = tid; t < T_; t += 32) {
            float e = __expf(w[t] - mx);
            w[t] = e;
            sm += e;
        }
#pragma unroll
        for (int o = 16; o; o >>= 1) sm += __shfl_xor_sync(0xffffffffu, sm, o);
        float inv = 1.0f / sm;
        for (int t = tid; t < T_; t += 32) w[t] *= inv;
    }
    __syncthreads();
    for (int n = tid; n < N_; n += blockDim.x) {
        float acc = 0.0f;
#pragma unroll 4
        for (int t = 0; t < T_; t++)
            acc += w[t] * g_oP[((size_t)t * B_ + b) * N_ + n];
        g_a[(size_t)b * N_ + n] = acc;
    }
}

// ------------------------------- fused match-GRU step ----------------------
// gi = gihp[t] + a @ AihP^T ; gh = r @ WpM^T + bpM ; gate math ; masked r.
__global__ void match_step_k(const float* __restrict__ gihp_t,  // [B][1536]
                             const float* __restrict__ a_in,    // [B][512]
                             const float* __restrict__ r_prev,  // [B][512]
                             const float* __restrict__ mask_t,  // [B]
                             float* __restrict__ r_out) {
    __shared__ float As[16][36];
    __shared__ float Rs[16][36];
    __shared__ float WA[16][50];
    __shared__ float WR[16][50];
    int tid = threadIdx.x;
    int n0 = blockIdx.x * 16, b0 = blockIdx.y * 32;
    int j0 = n0 * 3;
    int tx = tid & 15, ty = tid >> 4;

    float accA[4][3], accR[4][3];
#pragma unroll
    for (int i = 0; i < 4; i++)
#pragma unroll
        for (int g = 0; g < 3; g++) { accA[i][g] = 0.0f; accR[i][g] = 0.0f; }

    for (int k0 = 0; k0 < N_; k0 += 16) {
        {
            int bl = tid >> 2, kq = (tid & 3) * 4;
            const float* ap = a_in   + (size_t)(b0 + bl) * N_ + k0 + kq;
            const float* rp = r_prev + (size_t)(b0 + bl) * N_ + k0 + kq;
#pragma unroll
            for (int i = 0; i < 4; i++) {
                As[kq + i][bl] = ap[i];
                Rs[kq + i][bl] = rp[i];
            }
        }
#pragma unroll
        for (int rr = 0; rr < 6; rr++) {
            int e = tid + rr * 128;
            int jl = e >> 4, kq = e & 15;
            WA[kq][jl] = g_AihP[(size_t)(j0 + jl) * N_ + k0 + kq];
            WR[kq][jl] = g_WpM [(size_t)(j0 + jl) * N_ + k0 + kq];
        }
        __syncthreads();
#pragma unroll
        for (int k = 0; k < 16; k++) {
            float av[4], rv[4], wa[3], wr[3];
#pragma unroll
            for (int i = 0; i < 4; i++) {
                av[i] = As[k][ty * 4 + i];
                rv[i] = Rs[k][ty * 4 + i];
            }
#pragma unroll
            for (int g = 0; g < 3; g++) {
                wa[g] = WA[k][tx * 3 + g];
                wr[g] = WR[k][tx * 3 + g];
            }
#pragma unroll
            for (int i = 0; i < 4; i++)
#pragma unroll
                for (int g = 0; g < 3; g++) {
                    accA[i][g] += av[i] * wa[g];
                    accR[i][g] += rv[i] * wr[g];
                }
        }
        __syncthreads();
    }
    int n = n0 + tx;
    float br = g_bpM[j0 + tx * 3 + 0];
    float bz = g_bpM[j0 + tx * 3 + 1];
    float bn = g_bpM[j0 + tx * 3 + 2];
#pragma unroll
    for (int i = 0; i < 4; i++) {
        int b = b0 + ty * 4 + i;
        float gir = gihp_t[(size_t)b * G_ + n]         + accA[i][0];
        float giz = gihp_t[(size_t)b * G_ + 512 + n]   + accA[i][1];
        float gin = gihp_t[(size_t)b * G_ + 1024 + n]  + accA[i][2];
        float rg = sigm_f(gir + accR[i][0] + br);
        float zg = sigm_f(giz + accR[i][1] + bz);
        float nn = tanh_f(gin + rg * (accR[i][2] + bn));
        float rp = r_prev[(size_t)b * N_ + n];
        float rr = (1.0f - zg) * nn + zg * rp;
        float m = mask_t[b];
        r_out[(size_t)b * N_ + n] = rr * m + rp * (1.0f - m);
    }
}

// ------------------------------- logits + log_softmax ----------------------
__global__ void logits_k(const float* __restrict__ r,
                         const float* __restrict__ W,   // [3][512]
                         const float* __restrict__ bo,  // [3]
                         float* __restrict__ out) {
    int b = blockIdx.x, lane = threadIdx.x;
    float a0 = 0.0f, a1 = 0.0f, a2 = 0.0f;
    for (int k = lane; k < N_; k += 32) {
        float rv = r[(size_t)b * N_ + k];
        a0 += rv * W[k];
        a1 += rv * W[512 + k];
        a2 += rv * W[1024 + k];
    }
#pragma unroll
    for (int o = 16; o; o >>= 1) {
        a0 += __shfl_xor_sync(0xffffffffu, a0, o);
        a1 += __shfl_xor_sync(0xffffffffu, a1, o);
        a2 += __shfl_xor_sync(0xffffffffu, a2, o);
    }
    if (lane == 0) {
        float l0 = a0 + bo[0], l1 = a1 + bo[1], l2 = a2 + bo[2];
        float mx = fmaxf(l0, fmaxf(l1, l2));
        float s = __expf(l0 - mx) + __expf(l1 - mx) + __expf(l2 - mx);
        float lg = mx + logf(s);
        out[b * 3 + 0] = l0 - lg;
        out[b * 3 + 1] = l1 - lg;
        out[b * 3 + 2] = l2 - lg;
    }
}

// ---------------------------------------------------------------------------
extern "C" void kernel_launch(void* const* d_in, const int* in_sizes, int n_in,
                              void* d_out, int out_size) {
    const int*   prem   = (const int*)  d_in[0];
    const int*   hyp    = (const int*)  d_in[1];
    const float* E      = (const float*)d_in[2];
    const float* p_Wih  = (const float*)d_in[3];
    const float* p_Whh  = (const float*)d_in[4];
    const float* p_bih  = (const float*)d_in[5];
    const float* p_bhh  = (const float*)d_in[6];
    const float* h_Wih  = (const float*)d_in[7];
    const float* h_Whh  = (const float*)d_in[8];
    const float* h_bih  = (const float*)d_in[9];
    const float* h_bhh  = (const float*)d_in[10];
    const float* m_Wih  = (const float*)d_in[11];
    const float* m_Whh  = (const float*)d_in[12];
    const float* m_bih  = (const float*)d_in[13];
    const float* m_bhh  = (const float*)d_in[14];
    const float* W_y    = (const float*)d_in[15];
    const float* W_h    = (const float*)d_in[16];
    const float* W_r    = (const float*)d_in[17];
    const float* W_alpha= (const float*)d_in[18];
    const float* out_W  = (const float*)d_in[19];
    const float* out_b  = (const float*)d_in[20];
    float* out = (float*)d_out;

    float *GiP, *GiH, *oP, *oH, *Yw, *hWh, *gihp;
    float *h0, *h1, *r0, *r1, *sP, *aP;
    float *WyT, *WhT, *WrT, *WpP, *bpP, *WpH, *bpH, *WpM, *bpM, *AihP, *mWihH;
    float *maskP, *maskH;
    cudaGetSymbolAddress((void**)&GiP,  g_GiP);
    cudaGetSymbolAddress((void**)&GiH,  g_GiH);
    cudaGetSymbolAddress((void**)&oP,   g_oP);
    cudaGetSymbolAddress((void**)&oH,   g_oH);
    cudaGetSymbolAddress((void**)&Yw,   g_Yw);
    cudaGetSymbolAddress((void**)&hWh,  g_hWh);
    cudaGetSymbolAddress((void**)&gihp, g_gihp);
    cudaGetSymbolAddress((void**)&h0,   g_h0);
    cudaGetSymbolAddress((void**)&h1,   g_h1);
    cudaGetSymbolAddress((void**)&r0,   g_r0);
    cudaGetSymbolAddress((void**)&r1,   g_r1);
    cudaGetSymbolAddress((void**)&sP,   g_s);
    cudaGetSymbolAddress((void**)&aP,   g_a);
    cudaGetSymbolAddress((void**)&WyT,  g_WyT);
    cudaGetSymbolAddress((void**)&WhT,  g_WhT);
    cudaGetSymbolAddress((void**)&WrT,  g_WrT);
    cudaGetSymbolAddress((void**)&WpP,  g_WpP);
    cudaGetSymbolAddress((void**)&bpP,  g_bpP);
    cudaGetSymbolAddress((void**)&WpH,  g_WpH);
    cudaGetSymbolAddress((void**)&bpH,  g_bpH);
    cudaGetSymbolAddress((void**)&WpM,  g_WpM);
    cudaGetSymbolAddress((void**)&bpM,  g_bpM);
    cudaGetSymbolAddress((void**)&AihP, g_AihP);
    cudaGetSymbolAddress((void**)&mWihH,g_mWihH);
    cudaGetSymbolAddress((void**)&maskP,g_maskP);
    cudaGetSymbolAddress((void**)&maskH,g_maskH);

    // ---- prep ----
    make_masks_k<<<64, 256>>>(prem, hyp);
    zero_state_k<<<256, 256>>>();
    transpose512_k<<<1024, 256>>>(W_y, WyT);
    transpose512_k<<<1024, 256>>>(W_h, WhT);
    transpose512_k<<<1024, 256>>>(W_r, WrT);
    pack_gate_k<<<3072, 256>>>(p_Whh, p_bhh, WpP, bpP, 512, 0);
    pack_gate_k<<<3072, 256>>>(h_Whh, h_bhh, WpH, bpH, 512, 0);
    pack_gate_k<<<3072, 256>>>(m_Whh, m_bhh, WpM, bpM, 512, 0);
    pack_gate_k<<<3072, 256>>>(m_Wih, nullptr, AihP, nullptr, 1024, 0);
    split_mwih_h_k<<<3072, 256>>>(m_Wih, mWihH);

    // ---- input-gate precompute (gather fused) ----
    dim3 gGi(G_ / 128, TBN_ / 128);   // (12, 128)
    gemm_big_k<<<gGi, 256>>>(E, prem, p_Wih, p_bih, GiP, TBN_, G_, E_);
    gemm_big_k<<<gGi, 256>>>(E, hyp,  h_Wih, h_bih, GiH, TBN_, G_, E_);

    // ---- premise GRU ----
    float* hb[2] = {h0, h1};
    int cur = 0;
    for (int t = 0; t < T_; t++) {
        gru_step_k<<<dim3(32, 4), 128>>>(
            GiP + (size_t)t * B_ * G_, hb[cur],
            t ? (oP + (size_t)(t - 1) * B_ * N_) : nullptr,
            WpP, bpP, maskP + t * B_,
            hb[cur ^ 1], oP + (size_t)t * B_ * N_, t == 0);
        cur ^= 1;
    }
    // ---- hypothesis GRU (h0 = premise final h, keeps ping-pong) ----
    for (int t = 0; t < T_; t++) {
        gru_step_k<<<dim3(32, 4), 128>>>(
            GiH + (size_t)t * B_ * G_, hb[cur],
            t ? (oH + (size_t)(t - 1) * B_ * N_) : nullptr,
            WpH, bpH, maskH + t * B_,
            hb[cur ^ 1], oH + (size_t)t * B_ * N_, t == 0);
        cur ^= 1;
    }

    // ---- attention precompute ----
    gemm_big_k<<<dim3(N_ / 128, TBN_ / 128), 256>>>(oP, nullptr, WyT, nullptr,
                                                    Yw, TBN_, N_, N_);
    gemm_big_k<<<dim3(N_ / 128, TBN_ / 128), 256>>>(oH, nullptr, WhT, nullptr,
                                                    hWh, TBN_, N_, N_);
    gemm_big_k<<<dim3(G_ / 128, TBN_ / 128), 256>>>(oH, nullptr, mWihH, m_bih,
                                                    gihp, TBN_, G_, N_);

    // ---- attention loop ----
    float* rb[2] = {r0, r1};
    int rc = 0;
    for (int t = 0; t < T_; t++) {
        // s = r @ W_r + hWh[t]
        gemm_small_k<<<dim3(8, 4), 128>>>(rb[rc], WrT, nullptr,
                                          hWh + (size_t)t * B_ * N_,
                                          sP, B_, N_, N_);
        attn_alpha_k<<<2048, 256>>>(W_alpha);
        attn_ctx_k<<<128, 256>>>();
        match_step_k<<<dim3(32, 4), 128>>>(gihp + (size_t)t * B_ * G_,
                                           aP, rb[rc], maskH + t * B_,
                                           rb[rc ^ 1]);
        rc ^= 1;
    }

    // ---- classifier ----
    logits_k<<<128, 32>>>(rb[rc], out_W, out_b, out);
    (void)in_sizes; (void)n_in; (void)out_size;
}

// round 5
// speedup vs baseline: 1.0457x; 1.0457x over previous
#include <cuda_runtime.h>
#include <cuda_bf16.h>
#include <math.h>

// ---------------------------------------------------------------------------
// RTE forward (word-by-word attention entailment model), fp32.
// B=128, T=128, NDIM=512, EMB=300, G=3*NDIM=1536, VOCAB=50000.
//
// R4 changes vs R2:
//   * tanh.approx.f32 (1 MUFU) in the attention alpha hot path (was EX2+RCP).
//   * alpha + softmax + context fused into ONE kernel (per-b block),
//     removing a launch + the alpha round trip per step.
// ---------------------------------------------------------------------------

#define B_   128
#define T_   128
#define N_   512
#define E_   300
#define G_   1536
#define TBN_ (T_ * B_)   // 16384

// ------------------------------- scratch (static device memory) ------------
__device__ float g_GiP[TBN_ * G_];     // premise input gates, [t*B+b][1536]
__device__ float g_GiH[TBN_ * G_];     // hypothesis input gates
__device__ float g_oP [TBN_ * N_];     // premise GRU outputs  [t][b][n]
__device__ float g_oH [TBN_ * N_];     // hypothesis GRU outputs
__device__ float g_Yw [TBN_ * N_];     // o_p @ W_y
__device__ float g_hWh[TBN_ * N_];     // o_h @ W_h
__device__ float g_gihp[TBN_ * G_];    // o_h @ mWih_h^T + m_bih
__device__ float g_h0[B_ * N_];        // hidden ping-pong
__device__ float g_h1[B_ * N_];
__device__ float g_r0[B_ * N_];        // match-GRU state ping-pong
__device__ float g_r1[B_ * N_];
__device__ float g_s  [B_ * N_];       // attention s per step
__device__ float g_a  [B_ * N_];       // context vector per step
__device__ float g_maskP[T_ * B_];
__device__ float g_maskH[T_ * B_];
__device__ float g_WyT[N_ * N_];
__device__ float g_WhT[N_ * N_];
__device__ float g_WrT[N_ * N_];
__device__ float g_WpP[G_ * N_];       // gate-packed p_Whh  (row n*3+g)
__device__ float g_bpP[G_];
__device__ float g_WpH[G_ * N_];       // gate-packed h_Whh
__device__ float g_bpH[G_];
__device__ float g_WpM[G_ * N_];       // gate-packed m_Whh
__device__ float g_bpM[G_];
__device__ float g_AihP[G_ * N_];      // gate-packed m_Wih[:, 0:512]
__device__ float g_mWihH[G_ * N_];     // m_Wih[:, 512:1024] (natural gate order)

// ------------------------------- math helpers ------------------------------
__device__ __forceinline__ float sigm_f(float x) {
    return 1.0f / (1.0f + __expf(-x));
}
__device__ __forceinline__ float tanh_f(float x) {
    float e = __expf(-2.0f * fabsf(x));
    float t = (1.0f - e) / (1.0f + e);
    return copysignf(t, x);
}
// single-MUFU hardware tanh (sm_75+): used only in the attention hot path
__device__ __forceinline__ float tanh_fast(float x) {
    float y;
    asm("tanh.approx.f32 %0, %1;" : "=f"(y) : "f"(x));
    return y;
}

// ------------------------------- prep kernels ------------------------------
__global__ void make_masks_k(const int* __restrict__ prem,
                             const int* __restrict__ hyp) {
    int i = blockIdx.x * blockDim.x + threadIdx.x;   // i = t*B + b
    if (i < T_ * B_) {
        int t = i >> 7, b = i & 127;
        g_maskP[i] = (prem[b * T_ + t] != 0) ? 1.0f : 0.0f;
        g_maskH[i] = (hyp [b * T_ + t] != 0) ? 1.0f : 0.0f;
    }
}

__global__ void zero_state_k() {
    int i = blockIdx.x * blockDim.x + threadIdx.x;
    if (i < B_ * N_) { g_h0[i] = 0.0f; g_r0[i] = 0.0f; }
}

__global__ void transpose512_k(const float* __restrict__ src,
                               float* __restrict__ dst) {
    int i = blockIdx.x * blockDim.x + threadIdx.x;
    if (i < N_ * N_) {
        int r = i >> 9, c = i & 511;
        dst[c * N_ + r] = src[i];
    }
}

// Wp[(n*3+g)*512 + k] = W[(g*512+n)*ld + coloff + k]
__global__ void pack_gate_k(const float* __restrict__ W,
                            const float* __restrict__ b,
                            float* __restrict__ Wp, float* __restrict__ bp,
                            int ld, int coloff) {
    int i = blockIdx.x * blockDim.x + threadIdx.x;
    if (i < G_ * N_) {
        int j = i >> 9;
        int k = i & 511;
        int n = j / 3, g = j - n * 3;
        Wp[i] = W[(size_t)(g * N_ + n) * ld + coloff + k];
        if (k == 0 && bp) bp[j] = b[g * N_ + n];
    }
}

__global__ void split_mwih_h_k(const float* __restrict__ mWih,
                               float* __restrict__ out) {
    int i = blockIdx.x * blockDim.x + threadIdx.x;
    if (i < G_ * N_) {
        int j = i >> 9, k = i & 511;
        out[i] = mWih[(size_t)j * 1024 + 512 + k];
    }
}

// ------------------------------- big GEMM ----------------------------------
// C[M,N] = Aeff @ Bt^T (+bias[n]) ; Aeff row m = gidx ? A[tok(m)] : A[m]
// tok(m) = gidx[(m%128)*128 + m/128]  (embedding gather fused)
// Tiles: 128x128, TK=16, 256 threads, 8x8 micro-tile.
__global__ void gemm_big_k(const float* __restrict__ A,
                           const int*   __restrict__ gidx,
                           const float* __restrict__ Bt,
                           const float* __restrict__ bias,
                           float* __restrict__ C,
                           int M, int N, int K) {
    __shared__ float As[16][132];
    __shared__ float Bs[16][132];
    int tid = threadIdx.x;
    int tx = tid & 15, ty = tid >> 4;
    int m0 = blockIdx.y * 128, n0 = blockIdx.x * 128;

    float acc[8][8];
#pragma unroll
    for (int i = 0; i < 8; i++)
#pragma unroll
        for (int j = 0; j < 8; j++) acc[i][j] = 0.0f;

    int arow = m0 + (tid >> 1);
    const float* abase;
    if (gidx) {
        int tok = gidx[(arow & 127) * 128 + (arow >> 7)];
        abase = A + (size_t)tok * K;
    } else {
        abase = A + (size_t)arow * K;
    }
    int brow = n0 + (tid >> 1);
    const float* bbase = Bt + (size_t)brow * K;
    int kk = (tid & 1) * 8;

    for (int k0 = 0; k0 < K; k0 += 16) {
#pragma unroll
        for (int i = 0; i < 8; i++) {
            int k = k0 + kk + i;
            As[kk + i][tid >> 1] = (k < K) ? abase[k] : 0.0f;
            Bs[kk + i][tid >> 1] = (k < K) ? bbase[k] : 0.0f;
        }
        __syncthreads();
#pragma unroll
        for (int k = 0; k < 16; k++) {
            float a[8], b[8];
#pragma unroll
            for (int i = 0; i < 8; i++) a[i] = As[k][ty * 8 + i];
#pragma unroll
            for (int j = 0; j < 8; j++) b[j] = Bs[k][tx * 8 + j];
#pragma unroll
            for (int i = 0; i < 8; i++)
#pragma unroll
                for (int j = 0; j < 8; j++) acc[i][j] += a[i] * b[j];
        }
        __syncthreads();
    }
#pragma unroll
    for (int i = 0; i < 8; i++) {
        int row = m0 + ty * 8 + i;
        if (row >= M) continue;
#pragma unroll
        for (int j = 0; j < 8; j++) {
            int col = n0 + tx * 8 + j;
            if (col >= N) continue;
            float v = acc[i][j];
            if (bias) v += bias[col];
            C[(size_t)row * N + col] = v;
        }
    }
}

// ------------------------------- small GEMM --------------------------------
// C[M,N] = A @ Bt^T (+bias[n]) (+addend[m][n]) ; tiles 32x64, 128 threads.
__global__ void gemm_small_k(const float* __restrict__ A,
                             const float* __restrict__ Bt,
                             const float* __restrict__ bias,
                             const float* __restrict__ addend,
                             float* __restrict__ C,
                             int M, int N, int K) {
    __shared__ float As[16][36];
    __shared__ float Bs[16][68];
    int tid = threadIdx.x;
    int tx = tid & 15, ty = tid >> 4;
    int m0 = blockIdx.y * 32, n0 = blockIdx.x * 64;

    float acc[4][4];
#pragma unroll
    for (int i = 0; i < 4; i++)
#pragma unroll
        for (int j = 0; j < 4; j++) acc[i][j] = 0.0f;

    for (int k0 = 0; k0 < K; k0 += 16) {
        {
            int r = tid >> 2, kq = (tid & 3) * 4;
            const float* ap = A + (size_t)(m0 + r) * K + k0 + kq;
#pragma unroll
            for (int i = 0; i < 4; i++) {
                int k = k0 + kq + i;
                As[kq + i][r] = (k < K) ? ap[i] : 0.0f;
            }
        }
        {
            int r = tid >> 1, kq = (tid & 1) * 8;
            const float* bp = Bt + (size_t)(n0 + r) * K + k0 + kq;
#pragma unroll
            for (int i = 0; i < 8; i++) {
                int k = k0 + kq + i;
                Bs[kq + i][r] = (k < K) ? bp[i] : 0.0f;
            }
        }
        __syncthreads();
#pragma unroll
        for (int k = 0; k < 16; k++) {
            float a[4], b[4];
#pragma unroll
            for (int i = 0; i < 4; i++) a[i] = As[k][ty * 4 + i];
#pragma unroll
            for (int j = 0; j < 4; j++) b[j] = Bs[k][tx * 4 + j];
#pragma unroll
            for (int i = 0; i < 4; i++)
#pragma unroll
                for (int j = 0; j < 4; j++) acc[i][j] += a[i] * b[j];
        }
        __syncthreads();
    }
#pragma unroll
    for (int i = 0; i < 4; i++) {
        int row = m0 + ty * 4 + i;
        if (row >= M) continue;
#pragma unroll
        for (int j = 0; j < 4; j++) {
            int col = n0 + tx * 4 + j;
            if (col >= N) continue;
            float v = acc[i][j];
            if (bias)   v += bias[col];
            if (addend) v += addend[(size_t)row * N + col];
            C[(size_t)row * N + col] = v;
        }
    }
}

// ------------------------------- fused GRU step ----------------------------
// gh = h_prev @ Wpack^T + bpack (gate-packed rows n*3+g), then gate math +
// masked h/o update. Grid: (N/16, B/32) = (32,4), 128 threads.
__global__ void gru_step_k(const float* __restrict__ Gi_t,     // [B][1536]
                           const float* __restrict__ h_prev,   // [B][512]
                           const float* __restrict__ o_prev,   // [B][512] | null
                           const float* __restrict__ Wpack,    // [1536][512]
                           const float* __restrict__ bpack,    // [1536]
                           const float* __restrict__ mask_t,   // [B]
                           float* __restrict__ h_out,
                           float* __restrict__ o_out,
                           int first) {
    __shared__ float Hs[16][36];
    __shared__ float Ws[16][50];
    int tid = threadIdx.x;
    int n0 = blockIdx.x * 16, b0 = blockIdx.y * 32;
    int j0 = n0 * 3;
    int tx = tid & 15, ty = tid >> 4;

    float acc[4][3];
#pragma unroll
    for (int i = 0; i < 4; i++)
#pragma unroll
        for (int g = 0; g < 3; g++) acc[i][g] = 0.0f;

    for (int k0 = 0; k0 < N_; k0 += 16) {
        {
            int bl = tid >> 2, kq = (tid & 3) * 4;
            const float* hp = h_prev + (size_t)(b0 + bl) * N_ + k0 + kq;
#pragma unroll
            for (int i = 0; i < 4; i++) Hs[kq + i][bl] = hp[i];
        }
#pragma unroll
        for (int rr = 0; rr < 6; rr++) {
            int e = tid + rr * 128;
            int jl = e >> 4, kq = e & 15;
            Ws[kq][jl] = Wpack[(size_t)(j0 + jl) * N_ + k0 + kq];
        }
        __syncthreads();
#pragma unroll
        for (int k = 0; k < 16; k++) {
            float h[4], w[3];
#pragma unroll
            for (int i = 0; i < 4; i++) h[i] = Hs[k][ty * 4 + i];
#pragma unroll
            for (int g = 0; g < 3; g++) w[g] = Ws[k][tx * 3 + g];
#pragma unroll
            for (int i = 0; i < 4; i++)
#pragma unroll
                for (int g = 0; g < 3; g++) acc[i][g] += h[i] * w[g];
        }
        __syncthreads();
    }
    int n = n0 + tx;
    float br = bpack[j0 + tx * 3 + 0];
    float bz = bpack[j0 + tx * 3 + 1];
    float bn = bpack[j0 + tx * 3 + 2];
#pragma unroll
    for (int i = 0; i < 4; i++) {
        int b = b0 + ty * 4 + i;
        float gir = Gi_t[(size_t)b * G_ + n];
        float giz = Gi_t[(size_t)b * G_ + 512 + n];
        float gin = Gi_t[(size_t)b * G_ + 1024 + n];
        float rg = sigm_f(gir + acc[i][0] + br);
        float zg = sigm_f(giz + acc[i][1] + bz);
        float nn = tanh_f(gin + rg * (acc[i][2] + bn));
        float hp = h_prev[(size_t)b * N_ + n];
        float hr = (1.0f - zg) * nn + zg * hp;
        float m = mask_t[b];
        h_out[(size_t)b * N_ + n] = hr * m + hp * (1.0f - m);
        o_out[(size_t)b * N_ + n] =
            first ? hr : (hr * m + o_prev[(size_t)b * N_ + n] * (1.0f - m));
    }
}

// ------------------- fused attention: alpha + softmax + context ------------
// One block per b (256 threads, 8 warps). Warp w handles t' = w, w+8, ...
//   logit[t'] = sum_n tanh(Yw[t'][b][n] + s[b][n]) * Walpha[n]
//              - 1000*(1-maskP[t'][b])
// then in-block softmax over t', then a[b][n] = sum_t' w[t'] * oP[t'][b][n].
__global__ void attn_fused_k(const float* __restrict__ Walpha) {
    __shared__ __align__(16) float s_sh[N_];
    __shared__ __align__(16) float wa_sh[N_];
    __shared__ float w[T_];
    int b = blockIdx.x, tid = threadIdx.x;

    for (int n = tid; n < N_; n += 256) {
        s_sh[n]  = g_s[(size_t)b * N_ + n];
        wa_sh[n] = Walpha[n];
    }
    __syncthreads();

    int warp = tid >> 5, lane = tid & 31;
    for (int tp = warp; tp < T_; tp += 8) {
        const float4* yw = (const float4*)(g_Yw + ((size_t)tp * B_ + b) * N_);
        const float4* sv4 = (const float4*)s_sh;
        const float4* wa4 = (const float4*)wa_sh;
        float acc = 0.0f;
#pragma unroll
        for (int i = 0; i < 4; i++) {
            int idx = lane + i * 32;     // 128 float4 per row
            float4 y = yw[idx];
            float4 sv = sv4[idx];
            float4 av = wa4[idx];
            acc += tanh_fast(y.x + sv.x) * av.x;
            acc += tanh_fast(y.y + sv.y) * av.y;
            acc += tanh_fast(y.z + sv.z) * av.z;
            acc += tanh_fast(y.w + sv.w) * av.w;
        }
#pragma unroll
        for (int o = 16; o; o >>= 1) acc += __shfl_xor_sync(0xffffffffu, acc, o);
        if (lane == 0)
            w[tp] = acc - 1000.0f * (1.0f - g_maskP[tp * B_ + b]);
    }
    __syncthreads();

    if (tid < 32) {
        float mx = -1e30f;
        for (int t = tid; t < T_; t += 32) mx = fmaxf(mx, w[t]);
#pragma unroll
        for (int o = 16; o; o >>= 1)
            mx = fmaxf(mx, __shfl_xor_sync(0xffffffffu, mx, o));
        float sm = 0.0f;
        for (int t = tid; t < T_; t += 32) {
            float e = __expf(w[t] - mx);
            w[t] = e;
            sm += e;
        }
#pragma unroll
        for (int o = 16; o; o >>= 1) sm += __shfl_xor_sync(0xffffffffu, sm, o);
        float inv = 1.0f / sm;
        for (int t = tid; t < T_; t += 32) w[t] *= inv;
    }
    __syncthreads();

    for (int n = tid; n < N_; n += 256) {
        float acc = 0.0f;
#pragma unroll 4
        for (int t = 0; t < T_; t++)
            acc += w[t] * g_oP[((size_t)t * B_ + b) * N_ + n];
        g_a[(size_t)b * N_ + n] = acc;
    }
}

// ------------------------------- fused match-GRU step ----------------------
// gi = gihp[t] + a @ AihP^T ; gh = r @ WpM^T + bpM ; gate math ; masked r.
__global__ void match_step_k(const float* __restrict__ gihp_t,  // [B][1536]
                             const float* __restrict__ a_in,    // [B][512]
                             const float* __restrict__ r_prev,  // [B][512]
                             const float* __restrict__ mask_t,  // [B]
                             float* __restrict__ r_out) {
    __shared__ float As[16][36];
    __shared__ float Rs[16][36];
    __shared__ float WA[16][50];
    __shared__ float WR[16][50];
    int tid = threadIdx.x;
    int n0 = blockIdx.x * 16, b0 = blockIdx.y * 32;
    int j0 = n0 * 3;
    int tx = tid & 15, ty = tid >> 4;

    float accA[4][3], accR[4][3];
#pragma unroll
    for (int i = 0; i < 4; i++)
#pragma unroll
        for (int g = 0; g < 3; g++) { accA[i][g] = 0.0f; accR[i][g] = 0.0f; }

    for (int k0 = 0; k0 < N_; k0 += 16) {
        {
            int bl = tid >> 2, kq = (tid & 3) * 4;
            const float* ap = a_in   + (size_t)(b0 + bl) * N_ + k0 + kq;
            const float* rp = r_prev + (size_t)(b0 + bl) * N_ + k0 + kq;
#pragma unroll
            for (int i = 0; i < 4; i++) {
                As[kq + i][bl] = ap[i];
                Rs[kq + i][bl] = rp[i];
            }
        }
#pragma unroll
        for (int rr = 0; rr < 6; rr++) {
            int e = tid + rr * 128;
            int jl = e >> 4, kq = e & 15;
            WA[kq][jl] = g_AihP[(size_t)(j0 + jl) * N_ + k0 + kq];
            WR[kq][jl] = g_WpM [(size_t)(j0 + jl) * N_ + k0 + kq];
        }
        __syncthreads();
#pragma unroll
        for (int k = 0; k < 16; k++) {
            float av[4], rv[4], wa[3], wr[3];
#pragma unroll
            for (int i = 0; i < 4; i++) {
                av[i] = As[k][ty * 4 + i];
                rv[i] = Rs[k][ty * 4 + i];
            }
#pragma unroll
            for (int g = 0; g < 3; g++) {
                wa[g] = WA[k][tx * 3 + g];
                wr[g] = WR[k][tx * 3 + g];
            }
#pragma unroll
            for (int i = 0; i < 4; i++)
#pragma unroll
                for (int g = 0; g < 3; g++) {
                    accA[i][g] += av[i] * wa[g];
                    accR[i][g] += rv[i] * wr[g];
                }
        }
        __syncthreads();
    }
    int n = n0 + tx;
    float br = g_bpM[j0 + tx * 3 + 0];
    float bz = g_bpM[j0 + tx * 3 + 1];
    float bn = g_bpM[j0 + tx * 3 + 2];
#pragma unroll
    for (int i = 0; i < 4; i++) {
        int b = b0 + ty * 4 + i;
        float gir = gihp_t[(size_t)b * G_ + n]         + accA[i][0];
        float giz = gihp_t[(size_t)b * G_ + 512 + n]   + accA[i][1];
        float gin = gihp_t[(size_t)b * G_ + 1024 + n]  + accA[i][2];
        float rg = sigm_f(gir + accR[i][0] + br);
        float zg = sigm_f(giz + accR[i][1] + bz);
        float nn = tanh_f(gin + rg * (accR[i][2] + bn));
        float rp = r_prev[(size_t)b * N_ + n];
        float rr = (1.0f - zg) * nn + zg * rp;
        float m = mask_t[b];
        r_out[(size_t)b * N_ + n] = rr * m + rp * (1.0f - m);
    }
}

// ------------------------------- logits + log_softmax ----------------------
__global__ void logits_k(const float* __restrict__ r,
                         const float* __restrict__ W,   // [3][512]
                         const float* __restrict__ bo,  // [3]
                         float* __restrict__ out) {
    int b = blockIdx.x, lane = threadIdx.x;
    float a0 = 0.0f, a1 = 0.0f, a2 = 0.0f;
    for (int k = lane; k < N_; k += 32) {
        float rv = r[(size_t)b * N_ + k];
        a0 += rv * W[k];
        a1 += rv * W[512 + k];
        a2 += rv * W[1024 + k];
    }
#pragma unroll
    for (int o = 16; o; o >>= 1) {
        a0 += __shfl_xor_sync(0xffffffffu, a0, o);
        a1 += __shfl_xor_sync(0xffffffffu, a1, o);
        a2 += __shfl_xor_sync(0xffffffffu, a2, o);
    }
    if (lane == 0) {
        float l0 = a0 + bo[0], l1 = a1 + bo[1], l2 = a2 + bo[2];
        float mx = fmaxf(l0, fmaxf(l1, l2));
        float s = __expf(l0 - mx) + __expf(l1 - mx) + __expf(l2 - mx);
        float lg = mx + logf(s);
        out[b * 3 + 0] = l0 - lg;
        out[b * 3 + 1] = l1 - lg;
        out[b * 3 + 2] = l2 - lg;
    }
}

// ---------------------------------------------------------------------------
extern "C" void kernel_launch(void* const* d_in, const int* in_sizes, int n_in,
                              void* d_out, int out_size) {
    const int*   prem   = (const int*)  d_in[0];
    const int*   hyp    = (const int*)  d_in[1];
    const float* E      = (const float*)d_in[2];
    const float* p_Wih  = (const float*)d_in[3];
    const float* p_Whh  = (const float*)d_in[4];
    const float* p_bih  = (const float*)d_in[5];
    const float* p_bhh  = (const float*)d_in[6];
    const float* h_Wih  = (const float*)d_in[7];
    const float* h_Whh  = (const float*)d_in[8];
    const float* h_bih  = (const float*)d_in[9];
    const float* h_bhh  = (const float*)d_in[10];
    const float* m_Wih  = (const float*)d_in[11];
    const float* m_Whh  = (const float*)d_in[12];
    const float* m_bih  = (const float*)d_in[13];
    const float* m_bhh  = (const float*)d_in[14];
    const float* W_y    = (const float*)d_in[15];
    const float* W_h    = (const float*)d_in[16];
    const float* W_r    = (const float*)d_in[17];
    const float* W_alpha= (const float*)d_in[18];
    const float* out_W  = (const float*)d_in[19];
    const float* out_b  = (const float*)d_in[20];
    float* out = (float*)d_out;

    float *GiP, *GiH, *oP, *oH, *Yw, *hWh, *gihp;
    float *h0, *h1, *r0, *r1, *sP, *aP;
    float *WyT, *WhT, *WrT, *WpP, *bpP, *WpH, *bpH, *WpM, *bpM, *AihP, *mWihH;
    float *maskP, *maskH;
    cudaGetSymbolAddress((void**)&GiP,  g_GiP);
    cudaGetSymbolAddress((void**)&GiH,  g_GiH);
    cudaGetSymbolAddress((void**)&oP,   g_oP);
    cudaGetSymbolAddress((void**)&oH,   g_oH);
    cudaGetSymbolAddress((void**)&Yw,   g_Yw);
    cudaGetSymbolAddress((void**)&hWh,  g_hWh);
    cudaGetSymbolAddress((void**)&gihp, g_gihp);
    cudaGetSymbolAddress((void**)&h0,   g_h0);
    cudaGetSymbolAddress((void**)&h1,   g_h1);
    cudaGetSymbolAddress((void**)&r0,   g_r0);
    cudaGetSymbolAddress((void**)&r1,   g_r1);
    cudaGetSymbolAddress((void**)&sP,   g_s);
    cudaGetSymbolAddress((void**)&aP,   g_a);
    cudaGetSymbolAddress((void**)&WyT,  g_WyT);
    cudaGetSymbolAddress((void**)&WhT,  g_WhT);
    cudaGetSymbolAddress((void**)&WrT,  g_WrT);
    cudaGetSymbolAddress((void**)&WpP,  g_WpP);
    cudaGetSymbolAddress((void**)&bpP,  g_bpP);
    cudaGetSymbolAddress((void**)&WpH,  g_WpH);
    cudaGetSymbolAddress((void**)&bpH,  g_bpH);
    cudaGetSymbolAddress((void**)&WpM,  g_WpM);
    cudaGetSymbolAddress((void**)&bpM,  g_bpM);
    cudaGetSymbolAddress((void**)&AihP, g_AihP);
    cudaGetSymbolAddress((void**)&mWihH,g_mWihH);
    cudaGetSymbolAddress((void**)&maskP,g_maskP);
    cudaGetSymbolAddress((void**)&maskH,g_maskH);

    // ---- prep ----
    make_masks_k<<<64, 256>>>(prem, hyp);
    zero_state_k<<<256, 256>>>();
    transpose512_k<<<1024, 256>>>(W_y, WyT);
    transpose512_k<<<1024, 256>>>(W_h, WhT);
    transpose512_k<<<1024, 256>>>(W_r, WrT);
    pack_gate_k<<<3072, 256>>>(p_Whh, p_bhh, WpP, bpP, 512, 0);
    pack_gate_k<<<3072, 256>>>(h_Whh, h_bhh, WpH, bpH, 512, 0);
    pack_gate_k<<<3072, 256>>>(m_Whh, m_bhh, WpM, bpM, 512, 0);
    pack_gate_k<<<3072, 256>>>(m_Wih, nullptr, AihP, nullptr, 1024, 0);
    split_mwih_h_k<<<3072, 256>>>(m_Wih, mWihH);

    // ---- input-gate precompute (gather fused) ----
    dim3 gGi(G_ / 128, TBN_ / 128);   // (12, 128)
    gemm_big_k<<<gGi, 256>>>(E, prem, p_Wih, p_bih, GiP, TBN_, G_, E_);
    gemm_big_k<<<gGi, 256>>>(E, hyp,  h_Wih, h_bih, GiH, TBN_, G_, E_);

    // ---- premise GRU ----
    float* hb[2] = {h0, h1};
    int cur = 0;
    for (int t = 0; t < T_; t++) {
        gru_step_k<<<dim3(32, 4), 128>>>(
            GiP + (size_t)t * B_ * G_, hb[cur],
            t ? (oP + (size_t)(t - 1) * B_ * N_) : nullptr,
            WpP, bpP, maskP + t * B_,
            hb[cur ^ 1], oP + (size_t)t * B_ * N_, t == 0);
        cur ^= 1;
    }
    // ---- hypothesis GRU (h0 = premise final h, keeps ping-pong) ----
    for (int t = 0; t < T_; t++) {
        gru_step_k<<<dim3(32, 4), 128>>>(
            GiH + (size_t)t * B_ * G_, hb[cur],
            t ? (oH + (size_t)(t - 1) * B_ * N_) : nullptr,
            WpH, bpH, maskH + t * B_,
            hb[cur ^ 1], oH + (size_t)t * B_ * N_, t == 0);
        cur ^= 1;
    }

    // ---- attention precompute ----
    gemm_big_k<<<dim3(N_ / 128, TBN_ / 128), 256>>>(oP, nullptr, WyT, nullptr,
                                                    Yw, TBN_, N_, N_);
    gemm_big_k<<<dim3(N_ / 128, TBN_ / 128), 256>>>(oH, nullptr, WhT, nullptr,
                                                    hWh, TBN_, N_, N_);
    gemm_big_k<<<dim3(G_ / 128, TBN_ / 128), 256>>>(oH, nullptr, mWihH, m_bih,
                                                    gihp, TBN_, G_, N_);

    // ---- attention loop ----
    float* rb[2] = {r0, r1};
    int rc = 0;
    for (int t = 0; t < T_; t++) {
        // s = r @ W_r + hWh[t]
        gemm_small_k<<<dim3(8, 4), 128>>>(rb[rc], WrT, nullptr,
                                          hWh + (size_t)t * B_ * N_,
                                          sP, B_, N_, N_);
        // alpha + softmax + context, fused (one block per b)
        attn_fused_k<<<128, 256>>>(W_alpha);
        match_step_k<<<dim3(32, 4), 128>>>(gihp + (size_t)t * B_ * G_,
                                           aP, rb[rc], maskH + t * B_,
                                           rb[rc ^ 1]);
        rc ^= 1;
    }

    // ---- classifier ----
    logits_k<<<128, 32>>>(rb[rc], out_W, out_b, out);
    (void)in_sizes; (void)n_in; (void)out_size;
}

// round 6
// speedup vs baseline: 1.2702x; 1.2147x over previous
#include <cuda_runtime.h>
#include <cuda_bf16.h>
#include <math.h>

// ---------------------------------------------------------------------------
// RTE forward (word-by-word attention entailment model), fp32.
// B=128, T=128, NDIM=512, EMB=300, G=3*NDIM=1536, VOCAB=50000.
//
// R5: persistent kernels for both sequential loops (software grid barrier,
// 128 blocks <= 148 SMs so all blocks are co-resident). 656 launches -> 16.
// Cross-block dynamic state is read with __ldcg (L1 bypass); release via
// __threadfence before barrier arrive. Read-only weights keep L1 warm across
// steps (no per-launch L1 flush anymore).
// ---------------------------------------------------------------------------

#define B_   128
#define T_   128
#define N_   512
#define E_   300
#define G_   1536
#define TBN_ (T_ * B_)   // 16384
#define NBLK 128u

// ------------------------------- scratch (static device memory) ------------
__device__ float g_GiP[TBN_ * G_];
__device__ float g_GiH[TBN_ * G_];
__device__ float g_oP [TBN_ * N_];
__device__ float g_oH [TBN_ * N_];
__device__ float g_Yw [TBN_ * N_];
__device__ float g_hWh[TBN_ * N_];
__device__ float g_gihp[TBN_ * G_];
__device__ float g_h0[B_ * N_];
__device__ float g_h1[B_ * N_];
__device__ float g_r0[B_ * N_];
__device__ float g_r1[B_ * N_];
__device__ float g_s  [B_ * N_];
__device__ float g_a  [B_ * N_];
__device__ float g_maskP[T_ * B_];
__device__ float g_maskH[T_ * B_];
__device__ float g_WyT[N_ * N_];
__device__ float g_WhT[N_ * N_];
__device__ float g_WrT[N_ * N_];
__device__ float g_WpP[G_ * N_];
__device__ float g_bpP[G_];
__device__ float g_WpH[G_ * N_];
__device__ float g_bpH[G_];
__device__ float g_WpM[G_ * N_];
__device__ float g_bpM[G_];
__device__ float g_AihP[G_ * N_];
__device__ float g_mWihH[G_ * N_];
__device__ unsigned g_barA;
__device__ unsigned g_barB;

// ------------------------------- math helpers ------------------------------
__device__ __forceinline__ float sigm_f(float x) {
    return 1.0f / (1.0f + __expf(-x));
}
__device__ __forceinline__ float tanh_f(float x) {
    float e = __expf(-2.0f * fabsf(x));
    float t = (1.0f - e) / (1.0f + e);
    return copysignf(t, x);
}
__device__ __forceinline__ float tanh_fast(float x) {
    float y;
    asm("tanh.approx.f32 %0, %1;" : "=f"(y) : "f"(x));
    return y;
}

// ------------------------------- grid barrier ------------------------------
// All 128 blocks are co-resident (1 small block per SM, 148 SMs). Monotonic
// counter, reset by zero_state_k at the start of every kernel_launch replay.
__device__ __forceinline__ void grid_bar(unsigned* ctr, unsigned target) {
    __threadfence();                     // release this thread's stores
    __syncthreads();                     // all threads of CTA fenced
    if (threadIdx.x == 0) {
        atomicAdd(ctr, 1u);
        while (*(volatile unsigned*)ctr < target) __nanosleep(64);
    }
    __syncthreads();
}

// ------------------------------- prep kernels ------------------------------
__global__ void make_masks_k(const int* __restrict__ prem,
                             const int* __restrict__ hyp) {
    int i = blockIdx.x * blockDim.x + threadIdx.x;   // i = t*B + b
    if (i < T_ * B_) {
        int t = i >> 7, b = i & 127;
        g_maskP[i] = (prem[b * T_ + t] != 0) ? 1.0f : 0.0f;
        g_maskH[i] = (hyp [b * T_ + t] != 0) ? 1.0f : 0.0f;
    }
}

__global__ void zero_state_k() {
    int i = blockIdx.x * blockDim.x + threadIdx.x;
    if (i < B_ * N_) { g_h0[i] = 0.0f; g_r0[i] = 0.0f; }
    if (i == 0) { g_barA = 0u; g_barB = 0u; }
}

__global__ void transpose512_k(const float* __restrict__ src,
                               float* __restrict__ dst) {
    int i = blockIdx.x * blockDim.x + threadIdx.x;
    if (i < N_ * N_) {
        int r = i >> 9, c = i & 511;
        dst[c * N_ + r] = src[i];
    }
}

// Wp[(n*3+g)*512 + k] = W[(g*512+n)*ld + coloff + k]
__global__ void pack_gate_k(const float* __restrict__ W,
                            const float* __restrict__ b,
                            float* __restrict__ Wp, float* __restrict__ bp,
                            int ld, int coloff) {
    int i = blockIdx.x * blockDim.x + threadIdx.x;
    if (i < G_ * N_) {
        int j = i >> 9;
        int k = i & 511;
        int n = j / 3, g = j - n * 3;
        Wp[i] = W[(size_t)(g * N_ + n) * ld + coloff + k];
        if (k == 0 && bp) bp[j] = b[g * N_ + n];
    }
}

__global__ void split_mwih_h_k(const float* __restrict__ mWih,
                               float* __restrict__ out) {
    int i = blockIdx.x * blockDim.x + threadIdx.x;
    if (i < G_ * N_) {
        int j = i >> 9, k = i & 511;
        out[i] = mWih[(size_t)j * 1024 + 512 + k];
    }
}

// ------------------------------- big GEMM body -----------------------------
// C[M,N] = Aeff @ Bt^T (+bias[n]); Aeff row m = gidx ? A[tok(m)] : A[m].
// 128x128 tiles, TK=16, 256 threads, 8x8 micro-tile, float4 global loads.
// Requires K % 4 == 0 (K=300 or 512 here).
__device__ __forceinline__ void gemm_body(const float* __restrict__ A,
                                          const int*   __restrict__ gidx,
                                          const float* __restrict__ Bt,
                                          const float* __restrict__ bias,
                                          float* __restrict__ C,
                                          int M, int N, int K) {
    __shared__ float As[16][132];
    __shared__ float Bs[16][132];
    int tid = threadIdx.x;
    int tx = tid & 15, ty = tid >> 4;
    int m0 = blockIdx.y * 128, n0 = blockIdx.x * 128;

    float acc[8][8];
#pragma unroll
    for (int i = 0; i < 8; i++)
#pragma unroll
        for (int j = 0; j < 8; j++) acc[i][j] = 0.0f;

    int arow = m0 + (tid >> 1);
    const float* abase;
    if (gidx) {
        int tok = gidx[(arow & 127) * 128 + (arow >> 7)];
        abase = A + (size_t)tok * K;
    } else {
        abase = A + (size_t)arow * K;
    }
    int brow = n0 + (tid >> 1);
    const float* bbase = Bt + (size_t)brow * K;
    int kk = (tid & 1) * 8;
    int c = tid >> 1;

    for (int k0 = 0; k0 < K; k0 += 16) {
        float4 va0 = make_float4(0.f, 0.f, 0.f, 0.f), va1 = va0;
        float4 vb0 = va0, vb1 = va0;
        if (k0 + kk < K) {
            va0 = *(const float4*)(abase + k0 + kk);
            vb0 = *(const float4*)(bbase + k0 + kk);
        }
        if (k0 + kk + 4 < K) {
            va1 = *(const float4*)(abase + k0 + kk + 4);
            vb1 = *(const float4*)(bbase + k0 + kk + 4);
        }
        As[kk + 0][c] = va0.x; As[kk + 1][c] = va0.y;
        As[kk + 2][c] = va0.z; As[kk + 3][c] = va0.w;
        As[kk + 4][c] = va1.x; As[kk + 5][c] = va1.y;
        As[kk + 6][c] = va1.z; As[kk + 7][c] = va1.w;
        Bs[kk + 0][c] = vb0.x; Bs[kk + 1][c] = vb0.y;
        Bs[kk + 2][c] = vb0.z; Bs[kk + 3][c] = vb0.w;
        Bs[kk + 4][c] = vb1.x; Bs[kk + 5][c] = vb1.y;
        Bs[kk + 6][c] = vb1.z; Bs[kk + 7][c] = vb1.w;
        __syncthreads();
#pragma unroll
        for (int k = 0; k < 16; k++) {
            float a[8], b[8];
#pragma unroll
            for (int i = 0; i < 8; i++) a[i] = As[k][ty * 8 + i];
#pragma unroll
            for (int j = 0; j < 8; j++) b[j] = Bs[k][tx * 8 + j];
#pragma unroll
            for (int i = 0; i < 8; i++)
#pragma unroll
                for (int j = 0; j < 8; j++) acc[i][j] += a[i] * b[j];
        }
        __syncthreads();
    }
#pragma unroll
    for (int i = 0; i < 8; i++) {
        int row = m0 + ty * 8 + i;
#pragma unroll
        for (int j = 0; j < 8; j++) {
            int col = n0 + tx * 8 + j;
            float v = acc[i][j];
            if (bias) v += bias[col];
            C[(size_t)row * N + col] = v;
        }
    }
}

// z=0: premise Gi, z=1: hypothesis Gi
__global__ void gemm_gi_k(const int* __restrict__ prem,
                          const int* __restrict__ hyp,
                          const float* __restrict__ E,
                          const float* __restrict__ pWih,
                          const float* __restrict__ pbih,
                          const float* __restrict__ hWih,
                          const float* __restrict__ hbih) {
    int z = blockIdx.z;
    const int*   gidx = z ? hyp : prem;
    const float* Bt   = z ? hWih : pWih;
    const float* bias = z ? hbih : pbih;
    float*       Cc   = z ? g_GiH : g_GiP;
    gemm_body(E, gidx, Bt, bias, Cc, TBN_, G_, E_);
}

// z=0: Yw = oP@WyT^T, z=1: hWh = oH@WhT^T
__global__ void gemm_yh_k() {
    int z = blockIdx.z;
    const float* A  = z ? g_oH : g_oP;
    const float* Bt = z ? g_WhT : g_WyT;
    float*       Cc = z ? g_hWh : g_Yw;
    gemm_body(A, nullptr, Bt, nullptr, Cc, TBN_, N_, N_);
}

__global__ void gemm_gihp_k(const float* __restrict__ mbih) {
    gemm_body(g_oH, nullptr, g_mWihH, mbih, g_gihp, TBN_, G_, N_);
}

// ------------------------------- GRU step body -----------------------------
// 128 blocks (blk = 32 n-tiles x 4 b-tiles), 128 threads. h_prev via __ldcg
// (cross-block); Gi/weights/mask are static within the persistent kernel.
__device__ __forceinline__ void gru_step_body(
    const float* __restrict__ Gi_t, const float* __restrict__ h_prev,
    const float* __restrict__ o_prev, const float* __restrict__ Wpack,
    const float* __restrict__ bpack, const float* __restrict__ mask_t,
    float* __restrict__ h_out, float* __restrict__ o_out, int first,
    float (*Hs)[36], float (*Ws)[50]) {
    int tid = threadIdx.x;
    int n0 = (blockIdx.x & 31) * 16;
    int b0 = (blockIdx.x >> 5) * 32;
    int j0 = n0 * 3;
    int tx = tid & 15, ty = tid >> 4;

    float acc[4][3];
#pragma unroll
    for (int i = 0; i < 4; i++)
#pragma unroll
        for (int g = 0; g < 3; g++) acc[i][g] = 0.0f;

    for (int k0 = 0; k0 < N_; k0 += 16) {
        {
            int bl = tid >> 2, kq = (tid & 3) * 4;
            const float* hp = h_prev + (size_t)(b0 + bl) * N_ + k0 + kq;
#pragma unroll
            for (int i = 0; i < 4; i++) Hs[kq + i][bl] = __ldcg(hp + i);
        }
#pragma unroll
        for (int rr = 0; rr < 6; rr++) {
            int e = tid + rr * 128;
            int jl = e >> 4, kq = e & 15;
            Ws[kq][jl] = Wpack[(size_t)(j0 + jl) * N_ + k0 + kq];
        }
        __syncthreads();
#pragma unroll
        for (int k = 0; k < 16; k++) {
            float h[4], w[3];
#pragma unroll
            for (int i = 0; i < 4; i++) h[i] = Hs[k][ty * 4 + i];
#pragma unroll
            for (int g = 0; g < 3; g++) w[g] = Ws[k][tx * 3 + g];
#pragma unroll
            for (int i = 0; i < 4; i++)
#pragma unroll
                for (int g = 0; g < 3; g++) acc[i][g] += h[i] * w[g];
        }
        __syncthreads();
    }
    int n = n0 + tx;
    float br = bpack[j0 + tx * 3 + 0];
    float bz = bpack[j0 + tx * 3 + 1];
    float bn = bpack[j0 + tx * 3 + 2];
#pragma unroll
    for (int i = 0; i < 4; i++) {
        int b = b0 + ty * 4 + i;
        float gir = Gi_t[(size_t)b * G_ + n];
        float giz = Gi_t[(size_t)b * G_ + 512 + n];
        float gin = Gi_t[(size_t)b * G_ + 1024 + n];
        float rg = sigm_f(gir + acc[i][0] + br);
        float zg = sigm_f(giz + acc[i][1] + bz);
        float nn = tanh_f(gin + rg * (acc[i][2] + bn));
        float hp = __ldcg(h_prev + (size_t)b * N_ + n);
        float hr = (1.0f - zg) * nn + zg * hp;
        float m = mask_t[b];
        h_out[(size_t)b * N_ + n] = hr * m + hp * (1.0f - m);
        o_out[(size_t)b * N_ + n] =
            first ? hr : (hr * m + o_prev[(size_t)b * N_ + n] * (1.0f - m));
    }
}

// Persistent GRU: premise steps 0..127 then hypothesis steps 0..127.
__global__ void __launch_bounds__(128, 1) gru_persist_k() {
    __shared__ float Hs[16][36];
    __shared__ float Ws[16][50];
    unsigned tgt = 0;
    for (int s = 0; s < 256; s++) {
        const float* Gi  = (s < 128) ? g_GiP : g_GiH;
        const float* Wp  = (s < 128) ? g_WpP : g_WpH;
        const float* bp  = (s < 128) ? g_bpP : g_bpH;
        const float* msk = (s < 128) ? g_maskP : g_maskH;
        float* ob        = (s < 128) ? g_oP : g_oH;
        int t = s & 127;
        const float* hp = (s & 1) ? g_h1 : g_h0;
        float* ho       = (s & 1) ? g_h0 : g_h1;
        gru_step_body(Gi + (size_t)t * B_ * G_, hp,
                      t ? ob + (size_t)(t - 1) * B_ * N_ : nullptr,
                      Wp, bp, msk + t * B_, ho,
                      ob + (size_t)t * B_ * N_, t == 0, Hs, Ws);
        tgt += NBLK;
        grid_bar(&g_barA, tgt);
    }
}

// ------------------------------- attention phases --------------------------
// Phase A: s[b][n] = sum_k r[b][k] * WrT[n][k] + hWh[t][b][n]
// 128 blocks = 32 n-tiles(16) x 4 b-tiles(32); 256 threads, 2 outputs each.
__device__ __forceinline__ void attn_phaseA(int blk, int tid,
                                            const float* __restrict__ r_prev,
                                            int t, float (*Rs)[33],
                                            float (*Ws)[17]) {
    int n0 = (blk & 31) * 16;
    int b0 = (blk >> 5) * 32;
    int tx = tid & 15;      // n
    int ty = tid >> 4;      // 0..15 -> b pair
    float acc0 = 0.0f, acc1 = 0.0f;
    for (int k0 = 0; k0 < N_; k0 += 16) {
        {
            int bl = tid >> 3, kq = (tid & 7) * 2;
            const float* rp = r_prev + (size_t)(b0 + bl) * N_ + k0 + kq;
            Rs[kq][bl]     = __ldcg(rp);
            Rs[kq + 1][bl] = __ldcg(rp + 1);
            int nl = tid >> 4, kw = tid & 15;
            Ws[kw][nl] = g_WrT[(size_t)(n0 + nl) * N_ + k0 + kw];
        }
        __syncthreads();
#pragma unroll
        for (int k = 0; k < 16; k++) {
            float wv = Ws[k][tx];
            acc0 += Rs[k][ty * 2] * wv;
            acc1 += Rs[k][ty * 2 + 1] * wv;
        }
        __syncthreads();
    }
    int n = n0 + tx;
    int b = b0 + ty * 2;
    g_s[(size_t)b * N_ + n] =
        acc0 + g_hWh[((size_t)t * B_ + b) * N_ + n];
    g_s[(size_t)(b + 1) * N_ + n] =
        acc1 + g_hWh[((size_t)t * B_ + b + 1) * N_ + n];
}

// Phase B: per-b alpha (tanh dot) + softmax + context. block = b.
__device__ __forceinline__ void attn_phaseB(int b, int tid,
                                            const float* __restrict__ wa_sh,
                                            float* __restrict__ s_sh,
                                            float* __restrict__ w) {
    for (int n = tid; n < N_; n += 256)
        s_sh[n] = __ldcg(g_s + (size_t)b * N_ + n);
    __syncthreads();

    int warp = tid >> 5, lane = tid & 31;
    for (int tp = warp; tp < T_; tp += 8) {
        const float4* yw = (const float4*)(g_Yw + ((size_t)tp * B_ + b) * N_);
        const float4* sv4 = (const float4*)s_sh;
        const float4* wa4 = (const float4*)wa_sh;
        float acc = 0.0f;
#pragma unroll
        for (int i = 0; i < 4; i++) {
            int idx = lane + i * 32;
            float4 y = yw[idx];
            float4 sv = sv4[idx];
            float4 av = wa4[idx];
            acc += tanh_fast(y.x + sv.x) * av.x;
            acc += tanh_fast(y.y + sv.y) * av.y;
            acc += tanh_fast(y.z + sv.z) * av.z;
            acc += tanh_fast(y.w + sv.w) * av.w;
        }
#pragma unroll
        for (int o = 16; o; o >>= 1) acc += __shfl_xor_sync(0xffffffffu, acc, o);
        if (lane == 0)
            w[tp] = acc - 1000.0f * (1.0f - g_maskP[tp * B_ + b]);
    }
    __syncthreads();

    if (tid < 32) {
        float mx = -1e30f;
        for (int t = tid; t < T_; t += 32) mx = fmaxf(mx, w[t]);
#pragma unroll
        for (int o = 16; o; o >>= 1)
            mx = fmaxf(mx, __shfl_xor_sync(0xffffffffu, mx, o));
        float sm = 0.0f;
        for (int t = tid; t < T_; t += 32) {
            float e = __expf(w[t] - mx);
            w[t] = e;
            sm += e;
        }
#pragma unroll
        for (int o = 16; o; o >>= 1) sm += __shfl_xor_sync(0xffffffffu, sm, o);
        float inv = 1.0f / sm;
        for (int t = tid; t < T_; t += 32) w[t] *= inv;
    }
    __syncthreads();

    for (int n = tid; n < N_; n += 256) {
        float acc = 0.0f;
#pragma unroll 4
        for (int t = 0; t < T_; t++)
            acc += w[t] * g_oP[((size_t)t * B_ + b) * N_ + n];
        g_a[(size_t)b * N_ + n] = acc;
    }
}

// Phase C: match-GRU step. 128 blocks = 32 n-tiles x 4 b-tiles; 256 threads,
// 2 b-rows x 3 gates per thread, dual K=512 GEMM (a@AihP^T, r@WpM^T).
__device__ __forceinline__ void attn_phaseC(int blk, int tid,
                                            const float* __restrict__ gihp_t,
                                            const float* __restrict__ r_prev,
                                            const float* __restrict__ mask_t,
                                            float* __restrict__ r_out,
                                            float (*As)[36], float (*Rs)[36],
                                            float (*WA)[50], float (*WR)[50]) {
    int n0 = (blk & 31) * 16;
    int b0 = (blk >> 5) * 32;
    int j0 = n0 * 3;
    int tx = tid & 15, ty = tid >> 4;   // ty 0..15

    float accA[2][3], accR[2][3];
#pragma unroll
    for (int i = 0; i < 2; i++)
#pragma unroll
        for (int g = 0; g < 3; g++) { accA[i][g] = 0.0f; accR[i][g] = 0.0f; }

    for (int k0 = 0; k0 < N_; k0 += 16) {
        {
            int bl = tid >> 3, kq = (tid & 7) * 2;
            const float* ap = g_a    + (size_t)(b0 + bl) * N_ + k0 + kq;
            const float* rp = r_prev + (size_t)(b0 + bl) * N_ + k0 + kq;
            As[kq][bl]     = __ldcg(ap);
            As[kq + 1][bl] = __ldcg(ap + 1);
            Rs[kq][bl]     = __ldcg(rp);
            Rs[kq + 1][bl] = __ldcg(rp + 1);
        }
#pragma unroll
        for (int rr = 0; rr < 3; rr++) {
            int e = tid + rr * 256;
            int jl = e >> 4, kq = e & 15;
            WA[kq][jl] = g_AihP[(size_t)(j0 + jl) * N_ + k0 + kq];
            WR[kq][jl] = g_WpM [(size_t)(j0 + jl) * N_ + k0 + kq];
        }
        __syncthreads();
#pragma unroll
        for (int k = 0; k < 16; k++) {
            float av[2], rv[2], wa[3], wr[3];
#pragma unroll
            for (int i = 0; i < 2; i++) {
                av[i] = As[k][ty * 2 + i];
                rv[i] = Rs[k][ty * 2 + i];
            }
#pragma unroll
            for (int g = 0; g < 3; g++) {
                wa[g] = WA[k][tx * 3 + g];
                wr[g] = WR[k][tx * 3 + g];
            }
#pragma unroll
            for (int i = 0; i < 2; i++)
#pragma unroll
                for (int g = 0; g < 3; g++) {
                    accA[i][g] += av[i] * wa[g];
                    accR[i][g] += rv[i] * wr[g];
                }
        }
        __syncthreads();
    }
    int n = n0 + tx;
    float br = g_bpM[j0 + tx * 3 + 0];
    float bz = g_bpM[j0 + tx * 3 + 1];
    float bn = g_bpM[j0 + tx * 3 + 2];
#pragma unroll
    for (int i = 0; i < 2; i++) {
        int b = b0 + ty * 2 + i;
        float gir = gihp_t[(size_t)b * G_ + n]        + accA[i][0];
        float giz = gihp_t[(size_t)b * G_ + 512 + n]  + accA[i][1];
        float gin = gihp_t[(size_t)b * G_ + 1024 + n] + accA[i][2];
        float rg = sigm_f(gir + accR[i][0] + br);
        float zg = sigm_f(giz + accR[i][1] + bz);
        float nn = tanh_f(gin + rg * (accR[i][2] + bn));
        float rp = __ldcg(r_prev + (size_t)b * N_ + n);
        float rr = (1.0f - zg) * nn + zg * rp;
        float m = mask_t[b];
        r_out[(size_t)b * N_ + n] = rr * m + rp * (1.0f - m);
    }
}

// Persistent attention loop: 128 steps x (A: s-GEMM, B: alpha/softmax/ctx,
// C: match-GRU), grid barrier between phases. Final r lands in g_r0.
__global__ void __launch_bounds__(256, 1)
attn_persist_k(const float* __restrict__ Walpha) {
    __shared__ float Rs_a[16][33];
    __shared__ float Ws_a[16][17];
    __shared__ __align__(16) float s_sh[N_];
    __shared__ __align__(16) float wa_sh[N_];
    __shared__ float wgt[T_];
    __shared__ float As_c[16][36];
    __shared__ float Rs_c[16][36];
    __shared__ float WA_c[16][50];
    __shared__ float WR_c[16][50];
    int blk = blockIdx.x, tid = threadIdx.x;

    for (int n = tid; n < N_; n += 256) wa_sh[n] = Walpha[n];
    __syncthreads();

    unsigned tgt = 0;
    for (int t = 0; t < T_; t++) {
        const float* r_prev = (t & 1) ? g_r1 : g_r0;
        float* r_out        = (t & 1) ? g_r0 : g_r1;
        attn_phaseA(blk, tid, r_prev, t, Rs_a, Ws_a);
        tgt += NBLK; grid_bar(&g_barB, tgt);
        attn_phaseB(blk, tid, wa_sh, s_sh, wgt);
        tgt += NBLK; grid_bar(&g_barB, tgt);
        attn_phaseC(blk, tid, g_gihp + (size_t)t * B_ * G_, r_prev,
                    g_maskH + t * B_, r_out, As_c, Rs_c, WA_c, WR_c);
        tgt += NBLK; grid_bar(&g_barB, tgt);
    }
    // T_=128 even -> final write was to g_r0
}

// ------------------------------- logits + log_softmax ----------------------
__global__ void logits_k(const float* __restrict__ W,   // [3][512]
                         const float* __restrict__ bo,  // [3]
                         float* __restrict__ out) {
    int b = blockIdx.x, lane = threadIdx.x;
    float a0 = 0.0f, a1 = 0.0f, a2 = 0.0f;
    for (int k = lane; k < N_; k += 32) {
        float rv = g_r0[(size_t)b * N_ + k];
        a0 += rv * W[k];
        a1 += rv * W[512 + k];
        a2 += rv * W[1024 + k];
    }
#pragma unroll
    for (int o = 16; o; o >>= 1) {
        a0 += __shfl_xor_sync(0xffffffffu, a0, o);
        a1 += __shfl_xor_sync(0xffffffffu, a1, o);
        a2 += __shfl_xor_sync(0xffffffffu, a2, o);
    }
    if (lane == 0) {
        float l0 = a0 + bo[0], l1 = a1 + bo[1], l2 = a2 + bo[2];
        float mx = fmaxf(l0, fmaxf(l1, l2));
        float s = __expf(l0 - mx) + __expf(l1 - mx) + __expf(l2 - mx);
        float lg = mx + logf(s);
        out[b * 3 + 0] = l0 - lg;
        out[b * 3 + 1] = l1 - lg;
        out[b * 3 + 2] = l2 - lg;
    }
}

// ---------------------------------------------------------------------------
extern "C" void kernel_launch(void* const* d_in, const int* in_sizes, int n_in,
                              void* d_out, int out_size) {
    const int*   prem   = (const int*)  d_in[0];
    const int*   hyp    = (const int*)  d_in[1];
    const float* E      = (const float*)d_in[2];
    const float* p_Wih  = (const float*)d_in[3];
    const float* p_Whh  = (const float*)d_in[4];
    const float* p_bih  = (const float*)d_in[5];
    const float* p_bhh  = (const float*)d_in[6];
    const float* h_Wih  = (const float*)d_in[7];
    const float* h_Whh  = (const float*)d_in[8];
    const float* h_bih  = (const float*)d_in[9];
    const float* h_bhh  = (const float*)d_in[10];
    const float* m_Wih  = (const float*)d_in[11];
    const float* m_Whh  = (const float*)d_in[12];
    const float* m_bih  = (const float*)d_in[13];
    const float* m_bhh  = (const float*)d_in[14];
    const float* W_y    = (const float*)d_in[15];
    const float* W_h    = (const float*)d_in[16];
    const float* W_r    = (const float*)d_in[17];
    const float* W_alpha= (const float*)d_in[18];
    const float* out_W  = (const float*)d_in[19];
    const float* out_b  = (const float*)d_in[20];
    float* out = (float*)d_out;

    float *WyT, *WhT, *WrT, *WpP, *bpP, *WpH, *bpH, *WpM, *bpM, *AihP, *mWihH;
    cudaGetSymbolAddress((void**)&WyT,  g_WyT);
    cudaGetSymbolAddress((void**)&WhT,  g_WhT);
    cudaGetSymbolAddress((void**)&WrT,  g_WrT);
    cudaGetSymbolAddress((void**)&WpP,  g_WpP);
    cudaGetSymbolAddress((void**)&bpP,  g_bpP);
    cudaGetSymbolAddress((void**)&WpH,  g_WpH);
    cudaGetSymbolAddress((void**)&bpH,  g_bpH);
    cudaGetSymbolAddress((void**)&WpM,  g_WpM);
    cudaGetSymbolAddress((void**)&bpM,  g_bpM);
    cudaGetSymbolAddress((void**)&AihP, g_AihP);
    cudaGetSymbolAddress((void**)&mWihH,g_mWihH);

    // Launch order chosen so the ncu window (-s 5 -c 1) lands on a heavy
    // kernel (gemm_gi_k / gru_persist_k), not a prep transpose.
    zero_state_k<<<256, 256>>>();                                   // 1
    make_masks_k<<<64, 256>>>(prem, hyp);                           // 2
    pack_gate_k<<<3072, 256>>>(p_Whh, p_bhh, WpP, bpP, 512, 0);     // 3
    pack_gate_k<<<3072, 256>>>(h_Whh, h_bhh, WpH, bpH, 512, 0);     // 4
    gemm_gi_k<<<dim3(G_ / 128, TBN_ / 128, 2), 256>>>(              // 5
        prem, hyp, E, p_Wih, p_bih, h_Wih, h_bih);
    gru_persist_k<<<128, 128>>>();                                  // 6

    pack_gate_k<<<3072, 256>>>(m_Whh, m_bhh, WpM, bpM, 512, 0);     // 7
    pack_gate_k<<<3072, 256>>>(m_Wih, nullptr, AihP, nullptr, 1024, 0); // 8
    split_mwih_h_k<<<3072, 256>>>(m_Wih, mWihH);                    // 9
    transpose512_k<<<1024, 256>>>(W_y, WyT);                        // 10
    transpose512_k<<<1024, 256>>>(W_h, WhT);                        // 11
    transpose512_k<<<1024, 256>>>(W_r, WrT);                        // 12
    gemm_yh_k<<<dim3(N_ / 128, TBN_ / 128, 2), 256>>>();            // 13
    gemm_gihp_k<<<dim3(G_ / 128, TBN_ / 128), 256>>>(m_bih);        // 14

    attn_persist_k<<<128, 256>>>(W_alpha);                          // 15
    logits_k<<<128, 32>>>(out_W, out_b, out);                       // 16

    (void)in_sizes; (void)n_in; (void)out_size;
}

// round 7
// speedup vs baseline: 1.7657x; 1.3901x over previous
#include <cuda_runtime.h>
#include <cuda_bf16.h>
#include <math.h>

// ---------------------------------------------------------------------------
// RTE forward (word-by-word attention entailment model), fp32.
// B=128, T=128, NDIM=512, EMB=300, G=3*NDIM=1536, VOCAB=50000.
//
// R6:
//  * 7 launches total (prep fused); gru_persist_k sits at launch index 2
//    (the empirically ncu-profiled slot).
//  * gru_persist_k: 256 thr, Whh gate slice resident in dynamic smem (100KB,
//    loaded once per half), double-buffered __ldcg h prefetch, epilogue
//    operand prefetch.
//  * attn_persist_k: phase-C weight slices resident in dynamic smem (196KB,
//    loaded once), double-buffered prefetch in phases A and C.
// ---------------------------------------------------------------------------

#define B_   128
#define T_   128
#define N_   512
#define E_   300
#define G_   1536
#define TBN_ (T_ * B_)   // 16384
#define NBLK 128u

// ------------------------------- scratch (static device memory) ------------
__device__ float g_GiP[TBN_ * G_];
__device__ float g_GiH[TBN_ * G_];
__device__ float g_oP [TBN_ * N_];
__device__ float g_oH [TBN_ * N_];
__device__ float g_Yw [TBN_ * N_];
__device__ float g_hWh[TBN_ * N_];
__device__ float g_gihp[TBN_ * G_];
__device__ float g_h0[B_ * N_];
__device__ float g_h1[B_ * N_];
__device__ float g_r0[B_ * N_];
__device__ float g_r1[B_ * N_];
__device__ float g_s  [B_ * N_];
__device__ float g_a  [B_ * N_];
__device__ float g_maskP[T_ * B_];
__device__ float g_maskH[T_ * B_];
__device__ float g_WyT[N_ * N_];
__device__ float g_WhT[N_ * N_];
__device__ float g_WrT[N_ * N_];
__device__ float g_WpP[G_ * N_];
__device__ float g_bpP[G_];
__device__ float g_WpH[G_ * N_];
__device__ float g_bpH[G_];
__device__ float g_WpM[G_ * N_];
__device__ float g_bpM[G_];
__device__ float g_AihP[G_ * N_];
__device__ float g_mWihH[G_ * N_];
__device__ unsigned g_barA;
__device__ unsigned g_barB;

// ------------------------------- math helpers ------------------------------
__device__ __forceinline__ float sigm_f(float x) {
    return 1.0f / (1.0f + __expf(-x));
}
__device__ __forceinline__ float tanh_f(float x) {
    float e = __expf(-2.0f * fabsf(x));
    float t = (1.0f - e) / (1.0f + e);
    return copysignf(t, x);
}
__device__ __forceinline__ float tanh_fast(float x) {
    float y;
    asm("tanh.approx.f32 %0, %1;" : "=f"(y) : "f"(x));
    return y;
}

// ------------------------------- grid barrier ------------------------------
// 128 blocks, all co-resident (<=148 SMs, 1 block/SM at these smem sizes).
__device__ __forceinline__ void grid_bar(unsigned* ctr, unsigned target) {
    __threadfence();
    __syncthreads();
    if (threadIdx.x == 0) {
        atomicAdd(ctr, 1u);
        while (*(volatile unsigned*)ctr < target) __nanosleep(64);
    }
    __syncthreads();
}

// ------------------------------- fused prep --------------------------------
// Sections (linear index): masks | zero h0/r0/bars | 3x transpose | 3x pack |
// AihP pack | mWihH split.  Total 4,800,512 elements.
__global__ void prep_k(const int* __restrict__ prem,
                       const int* __restrict__ hyp,
                       const float* __restrict__ Wy,
                       const float* __restrict__ Wh,
                       const float* __restrict__ Wr,
                       const float* __restrict__ pWhh,
                       const float* __restrict__ pbhh,
                       const float* __restrict__ hWhh,
                       const float* __restrict__ hbhh,
                       const float* __restrict__ mWhh,
                       const float* __restrict__ mbhh,
                       const float* __restrict__ mWih) {
    long i = (long)blockIdx.x * 256 + threadIdx.x;
    if (i < 16384) {                                  // masks + bar reset
        int t = (int)i >> 7, b = (int)i & 127;
        g_maskP[i] = (prem[b * T_ + t] != 0) ? 1.0f : 0.0f;
        g_maskH[i] = (hyp [b * T_ + t] != 0) ? 1.0f : 0.0f;
        if (i == 0) { g_barA = 0u; g_barB = 0u; }
        return;
    }
    i -= 16384;
    if (i < 65536) { g_h0[i] = 0.0f; g_r0[i] = 0.0f; return; }
    i -= 65536;
    if (i < 3 * 262144) {                             // transposes
        int which = (int)(i >> 18);
        int e = (int)(i & 262143);
        int r = e >> 9, c = e & 511;
        const float* src = which == 0 ? Wy : (which == 1 ? Wh : Wr);
        float* dst = which == 0 ? g_WyT : (which == 1 ? g_WhT : g_WrT);
        dst[c * N_ + r] = src[e];
        return;
    }
    i -= 3 * 262144;
    if (i < 3 * 786432) {                             // gate packs (Whh x3)
        int which = (int)(i / 786432);
        int e = (int)(i - (long)which * 786432);
        int j = e >> 9, k = e & 511;
        int n = j / 3, g = j - n * 3;
        const float* W = which == 0 ? pWhh : (which == 1 ? hWhh : mWhh);
        const float* b = which == 0 ? pbhh : (which == 1 ? hbhh : mbhh);
        float* Wp = which == 0 ? g_WpP : (which == 1 ? g_WpH : g_WpM);
        float* bp = which == 0 ? g_bpP : (which == 1 ? g_bpH : g_bpM);
        Wp[e] = W[(size_t)(g * N_ + n) * N_ + k];
        if (k == 0) bp[j] = b[g * N_ + n];
        return;
    }
    i -= 3 * 786432;
    if (i < 786432) {                                 // AihP: mWih[:,0:512] packed
        int j = (int)i >> 9, k = (int)i & 511;
        int n = j / 3, g = j - n * 3;
        g_AihP[i] = mWih[(size_t)(g * N_ + n) * 1024 + k];
        return;
    }
    i -= 786432;
    if (i < 786432) {                                 // mWihH: mWih[:,512:1024]
        int j = (int)i >> 9, k = (int)i & 511;
        g_mWihH[i] = mWih[(size_t)j * 1024 + 512 + k];
        return;
    }
}

// ------------------------------- big GEMM body -----------------------------
__device__ __forceinline__ void gemm_body(const float* __restrict__ A,
                                          const int*   __restrict__ gidx,
                                          const float* __restrict__ Bt,
                                          const float* __restrict__ bias,
                                          float* __restrict__ C,
                                          int M, int N, int K) {
    __shared__ float As[16][132];
    __shared__ float Bs[16][132];
    int tid = threadIdx.x;
    int tx = tid & 15, ty = tid >> 4;
    int m0 = blockIdx.y * 128, n0 = blockIdx.x * 128;

    float acc[8][8];
#pragma unroll
    for (int i = 0; i < 8; i++)
#pragma unroll
        for (int j = 0; j < 8; j++) acc[i][j] = 0.0f;

    int arow = m0 + (tid >> 1);
    const float* abase;
    if (gidx) {
        int tok = gidx[(arow & 127) * 128 + (arow >> 7)];
        abase = A + (size_t)tok * K;
    } else {
        abase = A + (size_t)arow * K;
    }
    int brow = n0 + (tid >> 1);
    const float* bbase = Bt + (size_t)brow * K;
    int kk = (tid & 1) * 8;
    int c = tid >> 1;

    for (int k0 = 0; k0 < K; k0 += 16) {
        float4 va0 = make_float4(0.f, 0.f, 0.f, 0.f), va1 = va0;
        float4 vb0 = va0, vb1 = va0;
        if (k0 + kk < K) {
            va0 = *(const float4*)(abase + k0 + kk);
            vb0 = *(const float4*)(bbase + k0 + kk);
        }
        if (k0 + kk + 4 < K) {
            va1 = *(const float4*)(abase + k0 + kk + 4);
            vb1 = *(const float4*)(bbase + k0 + kk + 4);
        }
        As[kk + 0][c] = va0.x; As[kk + 1][c] = va0.y;
        As[kk + 2][c] = va0.z; As[kk + 3][c] = va0.w;
        As[kk + 4][c] = va1.x; As[kk + 5][c] = va1.y;
        As[kk + 6][c] = va1.z; As[kk + 7][c] = va1.w;
        Bs[kk + 0][c] = vb0.x; Bs[kk + 1][c] = vb0.y;
        Bs[kk + 2][c] = vb0.z; Bs[kk + 3][c] = vb0.w;
        Bs[kk + 4][c] = vb1.x; Bs[kk + 5][c] = vb1.y;
        Bs[kk + 6][c] = vb1.z; Bs[kk + 7][c] = vb1.w;
        __syncthreads();
#pragma unroll
        for (int k = 0; k < 16; k++) {
            float a[8], b[8];
#pragma unroll
            for (int i = 0; i < 8; i++) a[i] = As[k][ty * 8 + i];
#pragma unroll
            for (int j = 0; j < 8; j++) b[j] = Bs[k][tx * 8 + j];
#pragma unroll
            for (int i = 0; i < 8; i++)
#pragma unroll
                for (int j = 0; j < 8; j++) acc[i][j] += a[i] * b[j];
        }
        __syncthreads();
    }
#pragma unroll
    for (int i = 0; i < 8; i++) {
        int row = m0 + ty * 8 + i;
#pragma unroll
        for (int j = 0; j < 8; j++) {
            int col = n0 + tx * 8 + j;
            float v = acc[i][j];
            if (bias) v += bias[col];
            C[(size_t)row * N + col] = v;
        }
    }
}

__global__ void gemm_gi_k(const int* __restrict__ prem,
                          const int* __restrict__ hyp,
                          const float* __restrict__ E,
                          const float* __restrict__ pWih,
                          const float* __restrict__ pbih,
                          const float* __restrict__ hWih,
                          const float* __restrict__ hbih) {
    int z = blockIdx.z;
    gemm_body(E, z ? hyp : prem, z ? hWih : pWih, z ? hbih : pbih,
              z ? g_GiH : g_GiP, TBN_, G_, E_);
}

__global__ void gemm_yh_k() {
    int z = blockIdx.z;
    gemm_body(z ? g_oH : g_oP, nullptr, z ? g_WhT : g_WyT, nullptr,
              z ? g_hWh : g_Yw, TBN_, N_, N_);
}

__global__ void gemm_gihp_k(const float* __restrict__ mbih) {
    gemm_body(g_oH, nullptr, g_mWihH, mbih, g_gihp, TBN_, G_, N_);
}

// ------------------------------- persistent GRU ----------------------------
// 128 blocks x 256 threads. Block = (n-tile 16) x (b-tile 32). Whh gate slice
// (48 rows x 512) lives in dynamic smem [k*49 + j], loaded once per half.
extern __shared__ float dyn_smem[];

__global__ void __launch_bounds__(256, 1) gru_persist_k() {
    float* Wsm = dyn_smem;                 // 512*49 floats = 100,352 B
    __shared__ float Hs[16][34];
    __shared__ float bsm[48];
    int tid = threadIdx.x;
    int n0 = ((int)blockIdx.x & 31) * 16;
    int b0 = ((int)blockIdx.x >> 5) * 32;
    int j0 = n0 * 3;
    int tx = tid & 15, ty = tid >> 4;      // ty 0..15 -> 2 b-rows
    int bl = tid >> 3, kq = (tid & 7) * 2; // h loader lane
    int n = n0 + tx;
    unsigned tgt = 0;

    for (int half = 0; half < 2; half++) {
        const float* Gi  = half ? g_GiH : g_GiP;
        const float* Wp  = half ? g_WpH : g_WpP;
        const float* bp  = half ? g_bpH : g_bpP;
        const float* msk = half ? g_maskH : g_maskP;
        float* ob        = half ? g_oH : g_oP;

        // stage weight slice: Wsm[k*49 + j] = Wp[(j0+j)*512 + k]
        for (int i = tid; i < 48 * 512; i += 256) {
            int j = i >> 9, k = i & 511;
            Wsm[k * 49 + j] = Wp[(size_t)(j0 + j) * N_ + k];
        }
        if (tid < 48) bsm[tid] = bp[j0 + tid];
        __syncthreads();
        float br = bsm[tx * 3 + 0];
        float bz = bsm[tx * 3 + 1];
        float bn = bsm[tx * 3 + 2];

        for (int t = 0; t < T_; t++) {
            int s = half * T_ + t;
            const float* h_prev = (s & 1) ? g_h1 : g_h0;
            float* h_out        = (s & 1) ? g_h0 : g_h1;
            const float* Gi_t = Gi + (size_t)t * B_ * G_;
            float* o_out = ob + (size_t)t * B_ * N_;

            // ---- prefetch epilogue operands (fully hidden behind GEMM) ----
            float gi_r[2], gi_z[2], gi_n[2], mv[2], opv[2], hpv[2];
#pragma unroll
            for (int i = 0; i < 2; i++) {
                int b = b0 + ty * 2 + i;
                gi_r[i] = Gi_t[(size_t)b * G_ + n];
                gi_z[i] = Gi_t[(size_t)b * G_ + 512 + n];
                gi_n[i] = Gi_t[(size_t)b * G_ + 1024 + n];
                mv[i]   = msk[t * B_ + b];
                opv[i]  = t ? o_out[-(ptrdiff_t)(B_ * N_) + (size_t)b * N_ + n]
                            : 0.0f;
                hpv[i]  = __ldcg(h_prev + (size_t)b * N_ + n);
            }

            float acc[2][3];
#pragma unroll
            for (int i = 0; i < 2; i++)
#pragma unroll
                for (int g = 0; g < 3; g++) acc[i][g] = 0.0f;

            // double-buffered h chunk prefetch
            const float* hrow = h_prev + (size_t)(b0 + bl) * N_;
            float p0 = __ldcg(hrow + kq);
            float p1 = __ldcg(hrow + kq + 1);
            for (int k0 = 0; k0 < N_; k0 += 16) {
                Hs[kq][bl] = p0; Hs[kq + 1][bl] = p1;
                __syncthreads();
                if (k0 + 16 < N_) {
                    p0 = __ldcg(hrow + k0 + 16 + kq);
                    p1 = __ldcg(hrow + k0 + 16 + kq + 1);
                }
#pragma unroll
                for (int k = 0; k < 16; k++) {
                    const float* wr_ = &Wsm[(k0 + k) * 49 + tx * 3];
                    float w0 = wr_[0], w1 = wr_[1], w2 = wr_[2];
                    float h0v = Hs[k][ty * 2], h1v = Hs[k][ty * 2 + 1];
                    acc[0][0] += h0v * w0; acc[0][1] += h0v * w1;
                    acc[0][2] += h0v * w2;
                    acc[1][0] += h1v * w0; acc[1][1] += h1v * w1;
                    acc[1][2] += h1v * w2;
                }
                __syncthreads();
            }
#pragma unroll
            for (int i = 0; i < 2; i++) {
                int b = b0 + ty * 2 + i;
                float rg = sigm_f(gi_r[i] + acc[i][0] + br);
                float zg = sigm_f(gi_z[i] + acc[i][1] + bz);
                float nn = tanh_f(gi_n[i] + rg * (acc[i][2] + bn));
                float hp = hpv[i];
                float hr = (1.0f - zg) * nn + zg * hp;
                float m = mv[i];
                h_out[(size_t)b * N_ + n] = hr * m + hp * (1.0f - m);
                o_out[(size_t)b * N_ + n] =
                    (t == 0) ? hr : (hr * m + opv[i] * (1.0f - m));
            }
            tgt += NBLK;
            grid_bar(&g_barA, tgt);
        }
    }
}

// ------------------------------- persistent attention ----------------------
// 128 blocks x 256 threads. Phase C weight slices (AihP, WpM: 48x512 each)
// live in dynamic smem for the whole loop.
__global__ void __launch_bounds__(256, 1)
attn_persist_k(const float* __restrict__ Walpha) {
    float* WAs = dyn_smem;                  // 512*49
    float* WRs = dyn_smem + 512 * 49;       // 512*49  (total 200,704 B)
    __shared__ float Rs_a[16][34];
    __shared__ float Ws_a[16][17];
    __shared__ __align__(16) float s_sh[N_];
    __shared__ __align__(16) float wa_sh[N_];
    __shared__ float wgt[T_];
    __shared__ float As_c[16][34];
    __shared__ float Rs_c[16][34];

    int tid = threadIdx.x;
    int blk = blockIdx.x;
    int n0 = (blk & 31) * 16;
    int b0 = (blk >> 5) * 32;
    int j0 = n0 * 3;
    int tx = tid & 15, ty = tid >> 4;
    int bl = tid >> 3, kq = (tid & 7) * 2;
    int nl = tid >> 4, kw = tid & 15;       // phase-A weight loader
    int n = n0 + tx;
    int myb = blk;                          // phase-B batch row

    // stage phase-C weights once
    for (int i = tid; i < 48 * 512; i += 256) {
        int j = i >> 9, k = i & 511;
        WAs[k * 49 + j] = g_AihP[(size_t)(j0 + j) * N_ + k];
        WRs[k * 49 + j] = g_WpM [(size_t)(j0 + j) * N_ + k];
    }
    for (int i = tid; i < N_; i += 256) wa_sh[i] = Walpha[i];
    __syncthreads();
    float br = g_bpM[j0 + tx * 3 + 0];
    float bz = g_bpM[j0 + tx * 3 + 1];
    float bn = g_bpM[j0 + tx * 3 + 2];

    unsigned tgt = 0;
    for (int t = 0; t < T_; t++) {
        const float* r_prev = (t & 1) ? g_r1 : g_r0;
        float* r_out        = (t & 1) ? g_r0 : g_r1;

        // ================= phase A: s = r @ Wr^T + hWh[t] ==================
        {
            float ph0 = g_hWh[((size_t)t * B_ + b0 + ty * 2) * N_ + n];
            float ph1 = g_hWh[((size_t)t * B_ + b0 + ty * 2 + 1) * N_ + n];
            const float* rrow = r_prev + (size_t)(b0 + bl) * N_;
            float pr0 = __ldcg(rrow + kq);
            float pr1 = __ldcg(rrow + kq + 1);
            float pw  = g_WrT[(size_t)(n0 + nl) * N_ + kw];
            float acc0 = 0.0f, acc1 = 0.0f;
            for (int k0 = 0; k0 < N_; k0 += 16) {
                Rs_a[kq][bl] = pr0; Rs_a[kq + 1][bl] = pr1;
                Ws_a[kw][nl] = pw;
                __syncthreads();
                if (k0 + 16 < N_) {
                    pr0 = __ldcg(rrow + k0 + 16 + kq);
                    pr1 = __ldcg(rrow + k0 + 16 + kq + 1);
                    pw  = g_WrT[(size_t)(n0 + nl) * N_ + k0 + 16 + kw];
                }
#pragma unroll
                for (int k = 0; k < 16; k++) {
                    float wv = Ws_a[k][tx];
                    acc0 += Rs_a[k][ty * 2] * wv;
                    acc1 += Rs_a[k][ty * 2 + 1] * wv;
                }
                __syncthreads();
            }
            g_s[(size_t)(b0 + ty * 2) * N_ + n]     = acc0 + ph0;
            g_s[(size_t)(b0 + ty * 2 + 1) * N_ + n] = acc1 + ph1;
        }
        tgt += NBLK; grid_bar(&g_barB, tgt);

        // ============ phase B: alpha + softmax + context (block = b) =======
        {
            for (int i = tid; i < N_; i += 256)
                s_sh[i] = __ldcg(g_s + (size_t)myb * N_ + i);
            __syncthreads();

            int warp = tid >> 5, lane = tid & 31;
            for (int tp = warp; tp < T_; tp += 8) {
                const float4* yw =
                    (const float4*)(g_Yw + ((size_t)tp * B_ + myb) * N_);
                const float4* sv4 = (const float4*)s_sh;
                const float4* wa4 = (const float4*)wa_sh;
                float acc = 0.0f;
#pragma unroll
                for (int i = 0; i < 4; i++) {
                    int idx = lane + i * 32;
                    float4 y = yw[idx];
                    float4 sv = sv4[idx];
                    float4 av = wa4[idx];
                    acc += tanh_fast(y.x + sv.x) * av.x;
                    acc += tanh_fast(y.y + sv.y) * av.y;
                    acc += tanh_fast(y.z + sv.z) * av.z;
                    acc += tanh_fast(y.w + sv.w) * av.w;
                }
#pragma unroll
                for (int o = 16; o; o >>= 1)
                    acc += __shfl_xor_sync(0xffffffffu, acc, o);
                if (lane == 0)
                    wgt[tp] = acc - 1000.0f * (1.0f - g_maskP[tp * B_ + myb]);
            }
            __syncthreads();

            if (tid < 32) {
                float mx = -1e30f;
                for (int tt = tid; tt < T_; tt += 32) mx = fmaxf(mx, wgt[tt]);
#pragma unroll
                for (int o = 16; o; o >>= 1)
                    mx = fmaxf(mx, __shfl_xor_sync(0xffffffffu, mx, o));
                float sm = 0.0f;
                for (int tt = tid; tt < T_; tt += 32) {
                    float e = __expf(wgt[tt] - mx);
                    wgt[tt] = e;
                    sm += e;
                }
#pragma unroll
                for (int o = 16; o; o >>= 1)
                    sm += __shfl_xor_sync(0xffffffffu, sm, o);
                float inv = 1.0f / sm;
                for (int tt = tid; tt < T_; tt += 32) wgt[tt] *= inv;
            }
            __syncthreads();

            for (int nn = tid; nn < N_; nn += 256) {
                float acc = 0.0f;
#pragma unroll 4
                for (int tt = 0; tt < T_; tt++)
                    acc += wgt[tt] * g_oP[((size_t)tt * B_ + myb) * N_ + nn];
                g_a[(size_t)myb * N_ + nn] = acc;
            }
        }
        tgt += NBLK; grid_bar(&g_barB, tgt);

        // ================= phase C: match-GRU step =========================
        {
            const float* gihp_t = g_gihp + (size_t)t * B_ * G_;
            float gi_r[2], gi_z[2], gi_n[2], mv[2], rpv[2];
#pragma unroll
            for (int i = 0; i < 2; i++) {
                int b = b0 + ty * 2 + i;
                gi_r[i] = gihp_t[(size_t)b * G_ + n];
                gi_z[i] = gihp_t[(size_t)b * G_ + 512 + n];
                gi_n[i] = gihp_t[(size_t)b * G_ + 1024 + n];
                mv[i]   = g_maskH[t * B_ + b];
                rpv[i]  = __ldcg(r_prev + (size_t)b * N_ + n);
            }
            float accA[2][3], accR[2][3];
#pragma unroll
            for (int i = 0; i < 2; i++)
#pragma unroll
                for (int g = 0; g < 3; g++) {
                    accA[i][g] = 0.0f; accR[i][g] = 0.0f;
                }
            const float* arow = g_a    + (size_t)(b0 + bl) * N_;
            const float* rrow = r_prev + (size_t)(b0 + bl) * N_;
            float pa0 = __ldcg(arow + kq), pa1 = __ldcg(arow + kq + 1);
            float pr0 = __ldcg(rrow + kq), pr1 = __ldcg(rrow + kq + 1);
            for (int k0 = 0; k0 < N_; k0 += 16) {
                As_c[kq][bl] = pa0; As_c[kq + 1][bl] = pa1;
                Rs_c[kq][bl] = pr0; Rs_c[kq + 1][bl] = pr1;
                __syncthreads();
                if (k0 + 16 < N_) {
                    pa0 = __ldcg(arow + k0 + 16 + kq);
                    pa1 = __ldcg(arow + k0 + 16 + kq + 1);
                    pr0 = __ldcg(rrow + k0 + 16 + kq);
                    pr1 = __ldcg(rrow + k0 + 16 + kq + 1);
                }
#pragma unroll
                for (int k = 0; k < 16; k++) {
                    const float* wap = &WAs[(k0 + k) * 49 + tx * 3];
                    const float* wrp = &WRs[(k0 + k) * 49 + tx * 3];
                    float av0 = As_c[k][ty * 2], av1 = As_c[k][ty * 2 + 1];
                    float rv0 = Rs_c[k][ty * 2], rv1 = Rs_c[k][ty * 2 + 1];
#pragma unroll
                    for (int g = 0; g < 3; g++) {
                        float wa = wap[g], wr = wrp[g];
                        accA[0][g] += av0 * wa; accA[1][g] += av1 * wa;
                        accR[0][g] += rv0 * wr; accR[1][g] += rv1 * wr;
                    }
                }
                __syncthreads();
            }
#pragma unroll
            for (int i = 0; i < 2; i++) {
                int b = b0 + ty * 2 + i;
                float rg = sigm_f(gi_r[i] + accA[i][0] + accR[i][0] + br);
                float zg = sigm_f(gi_z[i] + accA[i][1] + accR[i][1] + bz);
                float nnv = tanh_f(gi_n[i] + accA[i][2] +
                                   rg * (accR[i][2] + bn));
                float rp = rpv[i];
                float rr = (1.0f - zg) * nnv + zg * rp;
                float m = mv[i];
                r_out[(size_t)b * N_ + n] = rr * m + rp * (1.0f - m);
            }
        }
        tgt += NBLK; grid_bar(&g_barB, tgt);
    }
}

// ------------------------------- logits + log_softmax ----------------------
__global__ void logits_k(const float* __restrict__ W,
                         const float* __restrict__ bo,
                         float* __restrict__ out) {
    int b = blockIdx.x, lane = threadIdx.x;
    float a0 = 0.0f, a1 = 0.0f, a2 = 0.0f;
    for (int k = lane; k < N_; k += 32) {
        float rv = g_r0[(size_t)b * N_ + k];
        a0 += rv * W[k];
        a1 += rv * W[512 + k];
        a2 += rv * W[1024 + k];
    }
#pragma unroll
    for (int o = 16; o; o >>= 1) {
        a0 += __shfl_xor_sync(0xffffffffu, a0, o);
        a1 += __shfl_xor_sync(0xffffffffu, a1, o);
        a2 += __shfl_xor_sync(0xffffffffu, a2, o);
    }
    if (lane == 0) {
        float l0 = a0 + bo[0], l1 = a1 + bo[1], l2 = a2 + bo[2];
        float mx = fmaxf(l0, fmaxf(l1, l2));
        float s = __expf(l0 - mx) + __expf(l1 - mx) + __expf(l2 - mx);
        float lg = mx + logf(s);
        out[b * 3 + 0] = l0 - lg;
        out[b * 3 + 1] = l1 - lg;
        out[b * 3 + 2] = l2 - lg;
    }
}

// ---------------------------------------------------------------------------
extern "C" void kernel_launch(void* const* d_in, const int* in_sizes, int n_in,
                              void* d_out, int out_size) {
    const int*   prem   = (const int*)  d_in[0];
    const int*   hyp    = (const int*)  d_in[1];
    const float* E      = (const float*)d_in[2];
    const float* p_Wih  = (const float*)d_in[3];
    const float* p_Whh  = (const float*)d_in[4];
    const float* p_bih  = (const float*)d_in[5];
    const float* p_bhh  = (const float*)d_in[6];
    const float* h_Wih  = (const float*)d_in[7];
    const float* h_Whh  = (const float*)d_in[8];
    const float* h_bih  = (const float*)d_in[9];
    const float* h_bhh  = (const float*)d_in[10];
    const float* m_Wih  = (const float*)d_in[11];
    const float* m_Whh  = (const float*)d_in[12];
    const float* m_bih  = (const float*)d_in[13];
    const float* m_bhh  = (const float*)d_in[14];
    const float* W_y    = (const float*)d_in[15];
    const float* W_h    = (const float*)d_in[16];
    const float* W_r    = (const float*)d_in[17];
    const float* W_alpha= (const float*)d_in[18];
    const float* out_W  = (const float*)d_in[19];
    const float* out_b  = (const float*)d_in[20];
    float* out = (float*)d_out;

    cudaFuncSetAttribute(gru_persist_k,
                         cudaFuncAttributeMaxDynamicSharedMemorySize,
                         512 * 49 * 4);
    cudaFuncSetAttribute(attn_persist_k,
                         cudaFuncAttributeMaxDynamicSharedMemorySize,
                         2 * 512 * 49 * 4);

    // 0: fused prep
    prep_k<<<18752, 256>>>(prem, hyp, W_y, W_h, W_r,
                           p_Whh, p_bhh, h_Whh, h_bhh, m_Whh, m_bhh, m_Wih);
    // 1: input-gate GEMMs (embedding gather fused), both sequences
    gemm_gi_k<<<dim3(G_ / 128, TBN_ / 128, 2), 256>>>(
        prem, hyp, E, p_Wih, p_bih, h_Wih, h_bih);
    // 2: persistent GRU (premise then hypothesis) — ncu-profiled slot
    gru_persist_k<<<128, 256, 512 * 49 * 4>>>();
    // 3: Yw and hWh GEMMs
    gemm_yh_k<<<dim3(N_ / 128, TBN_ / 128, 2), 256>>>();
    // 4: gihp GEMM
    gemm_gihp_k<<<dim3(G_ / 128, TBN_ / 128), 256>>>(m_bih);
    // 5: persistent attention + match-GRU loop
    attn_persist_k<<<128, 256, 2 * 512 * 49 * 4>>>(W_alpha);
    // 6: classifier
    logits_k<<<128, 32>>>(out_W, out_b, out);

    (void)in_sizes; (void)n_in; (void)out_size;
}